// round 3
// baseline (speedup 1.0000x reference)
#include <cuda_runtime.h>
#include <cuda_bf16.h>
#include <cstdint>

// ---------------------------------------------------------------------------
// EncoderSaliencySelection, GB300 sm_103a
//   B=32, N=4096, INPUT_DIM=125, ANCHOR_DIM=128, K_DIM=64, D_MODEL=1024,
//   HIDDEN=64, LAM=0.5, MAX_PROXY=256, EPS=1e-6
// Pipeline:
//   K1 mlp_kernel    : saliency[B*N]  (fused x@W1+b1 -> relu -> @W2+b2 -> sigmoid)
//   K2 batch_kernel  : per-batch cumsum, softmax (y_star -> out), bitonic top-256
//                      *** sort keyed on y_star (matches jax.lax.top_k input) ***
//   K3 lift_kernel   : dense anchor build + L2-norm + lift, ONLY at top-256 idx
//   K4 tokens_kernel : cloud[8192,64] @ proj_W[64,1024] + proj_b -> out
// Outputs: tokens (32*256*1024 f32) then y_star (32*4096 f32), concatenated.
// ---------------------------------------------------------------------------

#define Bq   32
#define Nq   4096
#define IDIM 125
#define ADIM 128
#define KDIM 64
#define DMOD 1024
#define HID  64
#define KEFF 256
#define EPSq 1e-6f

// scratch (no allocation allowed)
__device__ float g_sal [Bq * Nq];
__device__ float g_csal[Bq * Nq];
__device__ int   g_top [Bq * KEFF];
__device__ float g_cloud[Bq * KEFF * KDIM];

// packed f32x2 helpers (Blackwell). Element-wise exact fma, identical rounding
// to scalar __fmaf_rn per lane.
__device__ __forceinline__ unsigned long long pack_dup(float v) {
    unsigned long long r;
    asm("mov.b64 %0, {%1, %1};" : "=l"(r) : "f"(v));
    return r;
}
__device__ __forceinline__ void fma2(unsigned long long& acc,
                                     unsigned long long a, unsigned long long b) {
    asm("fma.rn.f32x2 %0, %1, %2, %0;" : "+l"(acc) : "l"(a), "l"(b));
}
__device__ __forceinline__ float lo32(unsigned long long v) {
    return __uint_as_float((unsigned)(v & 0xffffffffull));
}
__device__ __forceinline__ float hi32(unsigned long long v) {
    return __uint_as_float((unsigned)(v >> 32));
}

// ---------------------------------------------------------------------------
// K1: MLP scorer. One thread = one point. Layer 1: 32 packed accumulators
// (64 hidden units), ascending-d fma chain per unit (bit-equal to serial
// scalar fma). Layer 2: strict ascending serial __fmaf_rn over j=0..63.
// ---------------------------------------------------------------------------
#define CHUNK 25
__global__ __launch_bounds__(128)
void mlp_kernel(const float* __restrict__ x,  const float* __restrict__ W1,
                const float* __restrict__ b1, const float* __restrict__ W2,
                const float* __restrict__ b2)
{
    __shared__ float W1s[IDIM * HID];        // 32000 B
    __shared__ float Xs[128 * CHUNK];        // 12800 B
    __shared__ float b1s[HID], W2s[HID];

    const int tid = threadIdx.x;
    for (int i = tid; i < IDIM * HID; i += 128) W1s[i] = W1[i];
    if (tid < HID) { b1s[tid] = b1[tid]; W2s[tid] = W2[tid]; }

    const int p0 = blockIdx.x * 128;

    unsigned long long acc[32];
#pragma unroll
    for (int i = 0; i < 32; i++) acc[i] = 0ull;

    for (int cc = 0; cc < 5; cc++) {
        __syncthreads();
        for (int i = tid; i < 128 * CHUNK; i += 128) {
            int r = i / CHUNK, c = i % CHUNK;
            Xs[i] = x[(size_t)(p0 + r) * IDIM + cc * CHUNK + c];
        }
        __syncthreads();
#pragma unroll
        for (int c = 0; c < CHUNK; c++) {
            float xv = Xs[tid * CHUNK + c];      // stride-25 -> conflict-free
            unsigned long long xv2 = pack_dup(xv);
            const float* wrow = &W1s[(cc * CHUNK + c) * HID];
#pragma unroll
            for (int h4 = 0; h4 < 16; h4++) {
                ulonglong2 w = *reinterpret_cast<const ulonglong2*>(wrow + h4 * 4);
                fma2(acc[h4 * 2 + 0], xv2, w.x);
                fma2(acc[h4 * 2 + 1], xv2, w.y);
            }
        }
    }

    // layer 2: h_j = relu(acc_j + b1_j); score = serial ascending fma + b2
    float h[HID];
#pragma unroll
    for (int i = 0; i < 32; i++) {
        h[2 * i    ] = fmaxf(lo32(acc[i]) + b1s[2 * i    ], 0.f);
        h[2 * i + 1] = fmaxf(hi32(acc[i]) + b1s[2 * i + 1], 0.f);
    }
    float score = 0.f;
#pragma unroll
    for (int j = 0; j < HID; j++)
        score = __fmaf_rn(h[j], W2s[j], score);
    score += b2[0];
    g_sal[p0 + tid] = 1.f / (1.f + expf(-score));
}

// ---------------------------------------------------------------------------
// K2: per-batch cumsum + softmax(y_star) + bitonic top-256 keyed on y_star
// (desc, ties -> lower index: matches jax.lax.top_k on y_star).
// ---------------------------------------------------------------------------
__global__ __launch_bounds__(1024)
void batch_kernel(float* __restrict__ ystar_out)
{
    __shared__ float sv[Nq];     // 16 KB: saliency, then reused as y_star key
    __shared__ int   si[Nq];     // 16 KB
    __shared__ float tsum[1024]; //  4 KB

    const int b = blockIdx.x, t = threadIdx.x;
    const float* s = g_sal + (size_t)b * Nq;

    for (int i = t; i < Nq; i += 1024) sv[i] = s[i];
    __syncthreads();

    // ---- inclusive cumsum (thread owns [4t, 4t+4)) ----
    float s0 = sv[4 * t], s1 = sv[4 * t + 1], s2 = sv[4 * t + 2], s3 = sv[4 * t + 3];
    float l0 = s0, l1 = l0 + s1, l2 = l1 + s2, l3 = l2 + s3;
    tsum[t] = l3;
    __syncthreads();
    for (int off = 1; off < 1024; off <<= 1) {
        float v = tsum[t];
        float add = (t >= off) ? tsum[t - off] : 0.f;
        __syncthreads();
        tsum[t] = v + add;
        __syncthreads();
    }
    float pre = (t > 0) ? tsum[t - 1] : 0.f;
    const float invN = 1.f / (float)Nq;
    float* cs = g_csal + (size_t)b * Nq;
    cs[4 * t    ] = (pre + l0) * invN;
    cs[4 * t + 1] = (pre + l1) * invN;
    cs[4 * t + 2] = (pre + l2) * invN;
    cs[4 * t + 3] = (pre + l3) * invN;
    __syncthreads();

    // ---- softmax(saliency / 0.5) : s*2 is exact ----
    float mloc = fmaxf(fmaxf(s0, s1), fmaxf(s2, s3));
    tsum[t] = mloc;
    __syncthreads();
    for (int off = 512; off > 0; off >>= 1) {
        if (t < off) tsum[t] = fmaxf(tsum[t], tsum[t + off]);
        __syncthreads();
    }
    const float mz = tsum[0] * 2.0f;
    __syncthreads();
    float e0 = expf(s0 * 2.0f - mz);
    float e1 = expf(s1 * 2.0f - mz);
    float e2 = expf(s2 * 2.0f - mz);
    float e3 = expf(s3 * 2.0f - mz);
    tsum[t] = (e0 + e1) + (e2 + e3);
    __syncthreads();
    for (int off = 512; off > 0; off >>= 1) {
        if (t < off) tsum[t] = tsum[t] + tsum[t + off];
        __syncthreads();
    }
    const float S = tsum[0];
    float y0 = e0 / S, y1 = e1 / S, y2 = e2 / S, y3 = e3 / S;
    float* yo = ystar_out + (size_t)b * Nq;
    yo[4 * t    ] = y0;
    yo[4 * t + 1] = y1;
    yo[4 * t + 2] = y2;
    yo[4 * t + 3] = y3;
    __syncthreads();

    // ---- sort key = y_star (exact value jax.lax.top_k sees) ----
    sv[4 * t] = y0; sv[4 * t + 1] = y1; sv[4 * t + 2] = y2; sv[4 * t + 3] = y3;
    for (int i = t; i < Nq; i += 1024) si[i] = i;
    __syncthreads();

    // bitonic sort (desc by value, ties -> lower index first)
    for (unsigned k = 2; k <= Nq; k <<= 1) {
        for (unsigned j = k >> 1; j > 0; j >>= 1) {
            for (unsigned i = t; i < Nq; i += 1024) {
                unsigned ixj = i ^ j;
                if (ixj > i) {
                    float v1 = sv[i], v2 = sv[ixj];
                    int   i1 = si[i], i2 = si[ixj];
                    bool iFirst = (v1 > v2) || (v1 == v2 && i1 < i2);
                    bool up = ((i & k) == 0);
                    bool doswap = up ? (!iFirst) : iFirst;
                    if (doswap) {
                        sv[i] = v2; sv[ixj] = v1;
                        si[i] = i2; si[ixj] = i1;
                    }
                }
            }
            __syncthreads();
        }
    }
    if (t < KEFF) g_top[b * KEFF + t] = si[t];
}

// ---------------------------------------------------------------------------
// K3: gather top points, build dense anchor, normalize, lift -> cloud
// block = (batch b, group of 32 k). 256 threads: 4 groups x 64 lanes.
// ---------------------------------------------------------------------------
__global__ __launch_bounds__(256)
void lift_kernel(const float* __restrict__ x,
                 const float* __restrict__ liftW, const float* __restrict__ liftb,
                 const float* __restrict__ mu,    const float* __restrict__ sigma)
{
    __shared__ float Ws[ADIM * KDIM];   // 32 KB
    __shared__ float wsh[4][ADIM];
    __shared__ float red[4][2];
    __shared__ float mus[ADIM], rs[ADIM];
    __shared__ float lbs[KDIM];

    const int tid = threadIdx.x;
    for (int i = tid; i < ADIM * KDIM; i += 256) Ws[i] = liftW[i];
    if (tid < ADIM) { mus[tid] = mu[tid]; rs[tid] = 1.f / sigma[tid]; }
    if (tid < KDIM) lbs[tid] = liftb[tid];

    const int b     = blockIdx.x >> 3;
    const int kbase = (blockIdx.x & 7) * 32;
    const int g = tid >> 6;
    const int l = tid & 63;
    __syncthreads();

    for (int it = 0; it < 8; it++) {
        const int k   = kbase + it * 4 + g;
        const int idx = g_top[b * KEFF + k];
        const float* xr = x + ((size_t)b * Nq + idx) * IDIM;

        float v0 = xr[l];                      // a = l (< 125 always)
        const int a1 = l + 64;
        float v1;
        if (a1 < IDIM)        v1 = xr[a1];
        else if (a1 == 125)   v1 = g_sal [(size_t)b * Nq + idx];
        else if (a1 == 126)   v1 = (float)idx * (1.f / (float)(Nq - 1));
        else                  v1 = g_csal[(size_t)b * Nq + idx];

        float ss = v0 * v0 + v1 * v1;
#pragma unroll
        for (int o = 16; o > 0; o >>= 1) ss += __shfl_down_sync(0xffffffffu, ss, o);
        if ((tid & 31) == 0) red[g][(l >> 5) & 1] = ss;
        __syncthreads();

        const float sc = 1.f / (sqrtf(red[g][0] + red[g][1]) + EPSq);
        wsh[g][l ]  = (v0 * sc - mus[l ]) * rs[l ];
        wsh[g][a1]  = (v1 * sc - mus[a1]) * rs[a1];
        __syncthreads();

        float acc = lbs[l];
#pragma unroll 8
        for (int a = 0; a < ADIM; a++)
            acc += wsh[g][a] * Ws[a * KDIM + l];

        g_cloud[((size_t)b * KEFF + k) * KDIM + l] = acc;
        __syncthreads();
    }
}

// ---------------------------------------------------------------------------
// K4: tokens = cloud[8192,64] @ projW[64,1024] + projb
// 64x64 tile per 256-thread block, 4x4 reg tile with f32x2 packing.
// ---------------------------------------------------------------------------
__global__ __launch_bounds__(256)
void tokens_kernel(const float* __restrict__ projW, const float* __restrict__ projb,
                   float* __restrict__ out)
{
    __shared__ float As[64 * 65];   // As[c][r], padded
    __shared__ float Bs[64 * 64];   // Bs[c][d]

    const int tid = threadIdx.x;
    const int r0 = blockIdx.y * 64;
    const int d0 = blockIdx.x * 64;

    for (int i = tid; i < 4096; i += 256) {
        int r = i >> 6, c = i & 63;                       // c fast -> coalesced read
        As[c * 65 + r] = g_cloud[(size_t)(r0 + r) * KDIM + c];
    }
    for (int i = tid; i < 4096; i += 256) {
        int c = i >> 6, d = i & 63;                       // d fast -> coalesced read
        Bs[c * 64 + d] = projW[(size_t)c * DMOD + d0 + d];
    }
    __syncthreads();

    const int tx = tid & 15, ty = tid >> 4;

    unsigned long long acc[4][2];
#pragma unroll
    for (int i = 0; i < 4; i++) { acc[i][0] = 0ull; acc[i][1] = 0ull; }

#pragma unroll 8
    for (int c = 0; c < 64; c++) {
        ulonglong2 bv = *reinterpret_cast<const ulonglong2*>(&Bs[c * 64 + tx * 4]);
        const float* ap = &As[c * 65 + ty * 4];
#pragma unroll
        for (int i = 0; i < 4; i++) {
            unsigned long long a2 = pack_dup(ap[i]);
            fma2(acc[i][0], a2, bv.x);
            fma2(acc[i][1], a2, bv.y);
        }
    }

    float pb0 = projb[d0 + tx * 4 + 0];
    float pb1 = projb[d0 + tx * 4 + 1];
    float pb2 = projb[d0 + tx * 4 + 2];
    float pb3 = projb[d0 + tx * 4 + 3];
#pragma unroll
    for (int i = 0; i < 4; i++) {
        float4 o;
        o.x = lo32(acc[i][0]) + pb0;
        o.y = hi32(acc[i][0]) + pb1;
        o.z = lo32(acc[i][1]) + pb2;
        o.w = hi32(acc[i][1]) + pb3;
        size_t row = (size_t)(r0 + ty * 4 + i);
        *reinterpret_cast<float4*>(&out[row * DMOD + d0 + tx * 4]) = o;
    }
}

// ---------------------------------------------------------------------------
extern "C" void kernel_launch(void* const* d_in, const int* in_sizes, int n_in,
                              void* d_out, int out_size)
{
    const float* x     = (const float*)d_in[0];
    const float* W1    = (const float*)d_in[1];
    const float* b1    = (const float*)d_in[2];
    const float* W2    = (const float*)d_in[3];
    const float* b2    = (const float*)d_in[4];
    const float* liftW = (const float*)d_in[5];
    const float* liftb = (const float*)d_in[6];
    const float* mu    = (const float*)d_in[7];
    const float* sigma = (const float*)d_in[8];
    const float* projW = (const float*)d_in[9];
    const float* projb = (const float*)d_in[10];

    float* out    = (float*)d_out;
    float* tokens = out;                                   // [32,256,1024]
    float* ystar  = out + (size_t)Bq * KEFF * DMOD;        // [32,4096]

    mlp_kernel  <<<1024, 128>>>(x, W1, b1, W2, b2);
    batch_kernel<<<Bq, 1024>>>(ystar);
    lift_kernel <<<Bq * 8, 256>>>(x, liftW, liftb, mu, sigma);
    tokens_kernel<<<dim3(DMOD / 64, (Bq * KEFF) / 64), 256>>>(projW, projb, tokens);
}

// round 4
// speedup vs baseline: 1.0513x; 1.0513x over previous
#include <cuda_runtime.h>
#include <cuda_bf16.h>
#include <cstdint>

// ---------------------------------------------------------------------------
// EncoderSaliencySelection, GB300 sm_103a
//   B=32, N=4096, INPUT_DIM=125, ANCHOR_DIM=128, K_DIM=64, D_MODEL=1024,
//   HIDDEN=64, LAM=0.5, MAX_PROXY=256, EPS=1e-6
// ---------------------------------------------------------------------------

#define Bq   32
#define Nq   4096
#define IDIM 125
#define ADIM 128
#define KDIM 64
#define DMOD 1024
#define HID  64
#define KEFF 256
#define EPSq 1e-6f

__device__ float g_sal [Bq * Nq];
__device__ float g_csal[Bq * Nq];
__device__ int   g_top [Bq * KEFF];
__device__ float g_cloud[Bq * KEFF * KDIM];

// packed f32x2 helpers (element-wise exact: identical rounding to scalar fma)
__device__ __forceinline__ unsigned long long pack_dup(float v) {
    unsigned long long r;
    asm("mov.b64 %0, {%1, %1};" : "=l"(r) : "f"(v));
    return r;
}
__device__ __forceinline__ unsigned long long pack2(float a, float b) {
    unsigned long long r;
    asm("mov.b64 %0, {%1, %2};" : "=l"(r) : "f"(a), "f"(b));
    return r;
}
__device__ __forceinline__ void fma2(unsigned long long& acc,
                                     unsigned long long a, unsigned long long b) {
    asm("fma.rn.f32x2 %0, %1, %2, %0;" : "+l"(acc) : "l"(a), "l"(b));
}
__device__ __forceinline__ float lo32(unsigned long long v) {
    return __uint_as_float((unsigned)(v & 0xffffffffull));
}
__device__ __forceinline__ float hi32(unsigned long long v) {
    return __uint_as_float((unsigned)(v >> 32));
}

// ---------------------------------------------------------------------------
// K1: MLP scorer. 2 points per thread (W-reuse), 64 hidden units each.
// Layer-1 chains ascending-d per (point,unit); layer-2 strict serial fma.
// ---------------------------------------------------------------------------
#define CHUNK 25
__global__ __launch_bounds__(128)
void mlp_kernel(const float* __restrict__ x,  const float* __restrict__ W1,
                const float* __restrict__ b1, const float* __restrict__ W2,
                const float* __restrict__ b2)
{
    __shared__ float W1c[CHUNK * HID];     // 6400 B (per-chunk stage)
    __shared__ float Xs[256 * CHUNK];      // 25600 B
    __shared__ float b1s[HID], W2s[HID];

    const int tid = threadIdx.x;
    if (tid < HID) { b1s[tid] = b1[tid]; W2s[tid] = W2[tid]; }

    const int p0 = blockIdx.x * 256;

    unsigned long long acc0[32], acc1[32];
#pragma unroll
    for (int i = 0; i < 32; i++) { acc0[i] = 0ull; acc1[i] = 0ull; }

    for (int cc = 0; cc < 5; cc++) {
        __syncthreads();
        // stage W1 chunk: rows [cc*25, cc*25+25) of [125][64], contiguous
        for (int i = tid; i < (CHUNK * HID) / 4; i += 128)
            reinterpret_cast<float4*>(W1c)[i] =
                reinterpret_cast<const float4*>(W1 + cc * CHUNK * HID)[i];
        // stage X chunk: 256 points x 25 cols
        for (int i = tid; i < 256 * CHUNK; i += 128) {
            int r = i / CHUNK, c = i - r * CHUNK;
            Xs[i] = x[(size_t)(p0 + r) * IDIM + cc * CHUNK + c];
        }
        __syncthreads();
#pragma unroll
        for (int c = 0; c < CHUNK; c++) {
            unsigned long long xa = pack_dup(Xs[tid * CHUNK + c]);
            unsigned long long xb = pack_dup(Xs[(tid + 128) * CHUNK + c]);
            const float* wrow = &W1c[c * HID];
#pragma unroll
            for (int h4 = 0; h4 < 16; h4++) {
                ulonglong2 w = *reinterpret_cast<const ulonglong2*>(wrow + h4 * 4);
                fma2(acc0[2 * h4 + 0], xa, w.x);
                fma2(acc0[2 * h4 + 1], xa, w.y);
                fma2(acc1[2 * h4 + 0], xb, w.x);
                fma2(acc1[2 * h4 + 1], xb, w.y);
            }
        }
    }

    const float b2v = b2[0];
    // point 0
    {
        float h[HID];
#pragma unroll
        for (int i = 0; i < 32; i++) {
            h[2 * i    ] = fmaxf(lo32(acc0[i]) + b1s[2 * i    ], 0.f);
            h[2 * i + 1] = fmaxf(hi32(acc0[i]) + b1s[2 * i + 1], 0.f);
        }
        float score = 0.f;
#pragma unroll
        for (int j = 0; j < HID; j++) score = __fmaf_rn(h[j], W2s[j], score);
        score += b2v;
        g_sal[p0 + tid] = 1.f / (1.f + expf(-score));
    }
    // point 1
    {
        float h[HID];
#pragma unroll
        for (int i = 0; i < 32; i++) {
            h[2 * i    ] = fmaxf(lo32(acc1[i]) + b1s[2 * i    ], 0.f);
            h[2 * i + 1] = fmaxf(hi32(acc1[i]) + b1s[2 * i + 1], 0.f);
        }
        float score = 0.f;
#pragma unroll
        for (int j = 0; j < HID; j++) score = __fmaf_rn(h[j], W2s[j], score);
        score += b2v;
        g_sal[p0 + 128 + tid] = 1.f / (1.f + expf(-score));
    }
}

// ---------------------------------------------------------------------------
// K2: cumsum + softmax + exact top-256 (sort-chunks + prune-merge)
// comparator: total order (y desc, idx asc) == jax.lax.top_k on y_star
// ---------------------------------------------------------------------------
__device__ __forceinline__ void cswap(float* sv, int* si, int a, int b, bool up)
{
    float va = sv[a], vb = sv[b];
    int   ia = si[a], ib = si[b];
    bool aFirst = (va > vb) || (va == vb && ia < ib);
    if (aFirst != up) {
        sv[a] = vb; sv[b] = va;
        si[a] = ib; si[b] = ia;
    }
}

__global__ __launch_bounds__(1024)
void batch_kernel(float* __restrict__ ystar_out)
{
    __shared__ float sv[Nq];     // 16 KB
    __shared__ int   si[Nq];     // 16 KB
    __shared__ float tsum[1024]; //  4 KB

    const int b = blockIdx.x, t = threadIdx.x;
    const float* s = g_sal + (size_t)b * Nq;

    for (int i = t; i < Nq; i += 1024) sv[i] = s[i];
    __syncthreads();

    // ---- inclusive cumsum (thread owns [4t, 4t+4)) ----
    float s0 = sv[4 * t], s1 = sv[4 * t + 1], s2 = sv[4 * t + 2], s3 = sv[4 * t + 3];
    float l0 = s0, l1 = l0 + s1, l2 = l1 + s2, l3 = l2 + s3;
    tsum[t] = l3;
    __syncthreads();
    for (int off = 1; off < 1024; off <<= 1) {
        float v = tsum[t];
        float add = (t >= off) ? tsum[t - off] : 0.f;
        __syncthreads();
        tsum[t] = v + add;
        __syncthreads();
    }
    float pre = (t > 0) ? tsum[t - 1] : 0.f;
    const float invN = 1.f / (float)Nq;
    float* cs = g_csal + (size_t)b * Nq;
    cs[4 * t    ] = (pre + l0) * invN;
    cs[4 * t + 1] = (pre + l1) * invN;
    cs[4 * t + 2] = (pre + l2) * invN;
    cs[4 * t + 3] = (pre + l3) * invN;
    __syncthreads();

    // ---- softmax(saliency / 0.5) ----
    float mloc = fmaxf(fmaxf(s0, s1), fmaxf(s2, s3));
    tsum[t] = mloc;
    __syncthreads();
    for (int off = 512; off > 0; off >>= 1) {
        if (t < off) tsum[t] = fmaxf(tsum[t], tsum[t + off]);
        __syncthreads();
    }
    const float mz = tsum[0] * 2.0f;
    __syncthreads();
    float e0 = expf(s0 * 2.0f - mz);
    float e1 = expf(s1 * 2.0f - mz);
    float e2 = expf(s2 * 2.0f - mz);
    float e3 = expf(s3 * 2.0f - mz);
    tsum[t] = (e0 + e1) + (e2 + e3);
    __syncthreads();
    for (int off = 512; off > 0; off >>= 1) {
        if (t < off) tsum[t] = tsum[t] + tsum[t + off];
        __syncthreads();
    }
    const float S = tsum[0];
    float y0 = e0 / S, y1 = e1 / S, y2 = e2 / S, y3 = e3 / S;
    float* yo = ystar_out + (size_t)b * Nq;
    yo[4 * t    ] = y0;
    yo[4 * t + 1] = y1;
    yo[4 * t + 2] = y2;
    yo[4 * t + 3] = y3;
    __syncthreads();

    // ---- sort key = y_star ----
    sv[4 * t] = y0; sv[4 * t + 1] = y1; sv[4 * t + 2] = y2; sv[4 * t + 3] = y3;
#pragma unroll
    for (int e = 0; e < 4; e++) si[4 * t + e] = 4 * t + e;
    __syncthreads();

    // ===== phase 1: sort each 512-chunk descending =====
    // (a) k<=128: entirely within each warp's 128-elem span -> __syncwarp only
    for (unsigned k = 2; k <= 128; k <<= 1) {
        for (unsigned j = k >> 1; j > 0; j >>= 1) {
#pragma unroll
            for (int e = 0; e < 4; e++) {
                int i = 4 * t + e;
                if ((i & j) == 0) cswap(sv, si, i, i + j, (i & k) == 0);
            }
            __syncwarp();
        }
    }
    __syncthreads();
    // (b) k=256
    {
#pragma unroll
        for (int e = 0; e < 4; e++) {
            int i = 4 * t + e;
            if ((i & 128) == 0) cswap(sv, si, i, i + 128, (i & 256) == 0);
        }
        __syncthreads();
        for (unsigned j = 64; j > 0; j >>= 1) {
#pragma unroll
            for (int e = 0; e < 4; e++) {
                int i = 4 * t + e;
                if ((i & j) == 0) cswap(sv, si, i, i + j, (i & 256) == 0);
            }
            __syncwarp();
        }
        __syncthreads();
    }
    // (c) k=512 (chunk size): direction always "up" (descending)
    {
#pragma unroll
        for (int e = 0; e < 4; e++) {
            int i = 4 * t + e;
            if ((i & 256) == 0) cswap(sv, si, i, i + 256, true);
        }
        __syncthreads();
#pragma unroll
        for (int e = 0; e < 4; e++) {
            int i = 4 * t + e;
            if ((i & 128) == 0) cswap(sv, si, i, i + 128, true);
        }
        __syncthreads();
        for (unsigned j = 64; j > 0; j >>= 1) {
#pragma unroll
            for (int e = 0; e < 4; e++) {
                int i = 4 * t + e;
                if ((i & j) == 0) cswap(sv, si, i, i + j, true);
            }
            __syncwarp();
        }
        __syncthreads();
    }

    // ===== phase 2: keep top-256 of each 512-chunk, compact to [0,2048) =====
    {
        int d0 = t, d1 = t + 1024;
        int s0i = (d0 >> 8) * 512 + (d0 & 255);
        int s1i = (d1 >> 8) * 512 + (d1 & 255);
        float v0 = sv[s0i], v1 = sv[s1i];
        int   j0 = si[s0i], j1 = si[s1i];
        __syncthreads();
        sv[d0] = v0; si[d0] = j0;
        sv[d1] = v1; si[d1] = j1;
        __syncthreads();
    }

    // ===== phase 3: tree-merge 8 desc lists of 256, pruning to top-256 =====
    int m = 8;
    while (m > 1) {
        int pairs = m >> 1;
        // step A: bitonic cross-compare, winners -> [p*512, p*512+256)
        for (int idx = t; idx < pairs * 256; idx += 1024) {
            int p = idx >> 8, i = idx & 255;
            cswap(sv, si, p * 512 + i, p * 512 + 511 - i, true);
        }
        __syncthreads();
        // step B: clean bitonic top half
        for (int j = 128; j >= 1; j >>= 1) {
            for (int idx = t; idx < pairs * 128; idx += 1024) {
                int p = idx >> 7, r = idx & 127;
                int i = ((r & ~(j - 1)) << 1) | (r & (j - 1));
                cswap(sv, si, p * 512 + i, p * 512 + i + j, true);
            }
            __syncthreads();
        }
        // step C: compact winners to stride-256 lists
        if (m > 2) {
            int tot = pairs * 256;
            float mv = 0.f; int mi = 0; bool act = (t < tot);
            if (act) { int p = t >> 8, i = t & 255; mv = sv[p * 512 + i]; mi = si[p * 512 + i]; }
            __syncthreads();
            if (act) { sv[t] = mv; si[t] = mi; }
            __syncthreads();
        }
        m = pairs;
    }

    if (t < KEFF) g_top[b * KEFF + t] = si[t];
}

// ---------------------------------------------------------------------------
// K3: warp-per-point gather + normalize + lift. Lane l -> outputs {2l,2l+1}.
// ---------------------------------------------------------------------------
__global__ __launch_bounds__(256)
void lift_kernel(const float* __restrict__ x,
                 const float* __restrict__ liftW, const float* __restrict__ liftb,
                 const float* __restrict__ mu,    const float* __restrict__ sigma)
{
    __shared__ float Ws[ADIM * KDIM];   // 32 KB
    __shared__ float mus[ADIM], rs[ADIM], lbs[KDIM];
    __shared__ float wsh[8][ADIM];      // 4 KB

    const int tid = threadIdx.x;
    for (int i = tid; i < (ADIM * KDIM) / 4; i += 256)
        reinterpret_cast<float4*>(Ws)[i] = reinterpret_cast<const float4*>(liftW)[i];
    if (tid < ADIM) { mus[tid] = mu[tid]; rs[tid] = 1.f / sigma[tid]; }
    if (tid < KDIM) lbs[tid] = liftb[tid];

    const int w = tid >> 5, l = tid & 31;
    const int b     = blockIdx.x >> 3;
    const int kbase = (blockIdx.x & 7) * 32;
    __syncthreads();

    for (int it = 0; it < 4; it++) {
        const int k   = kbase + it * 8 + w;
        const int idx = g_top[b * KEFF + k];
        const float* xr = x + ((size_t)b * Nq + idx) * IDIM;

        float v[4];
#pragma unroll
        for (int q = 0; q < 4; q++) {
            int a = q * 32 + l;
            float val;
            if (a < IDIM)       val = xr[a];
            else if (a == 125)  val = g_sal [(size_t)b * Nq + idx];
            else if (a == 126)  val = (float)idx * (1.f / (float)(Nq - 1));
            else                val = g_csal[(size_t)b * Nq + idx];
            v[q] = val;
        }
        float ss = (v[0] * v[0] + v[1] * v[1]) + (v[2] * v[2] + v[3] * v[3]);
#pragma unroll
        for (int o = 16; o > 0; o >>= 1) ss += __shfl_xor_sync(0xffffffffu, ss, o);
        const float sc = 1.f / (sqrtf(ss) + EPSq);
#pragma unroll
        for (int q = 0; q < 4; q++) {
            int a = q * 32 + l;
            wsh[w][a] = (v[q] * sc - mus[a]) * rs[a];
        }
        __syncwarp();

        unsigned long long acc = pack2(lbs[2 * l], lbs[2 * l + 1]);
#pragma unroll 8
        for (int a = 0; a < ADIM; a++) {
            unsigned long long wpair =
                *reinterpret_cast<const unsigned long long*>(&Ws[a * KDIM + 2 * l]);
            fma2(acc, pack_dup(wsh[w][a]), wpair);
        }
        float2 o; o.x = lo32(acc); o.y = hi32(acc);
        *reinterpret_cast<float2*>(&g_cloud[((size_t)b * KEFF + k) * KDIM + 2 * l]) = o;
        __syncwarp();
    }
}

// ---------------------------------------------------------------------------
// K4: tokens = cloud[8192,64] @ projW[64,1024] + projb
// 64x128 tile, 256 threads, 4x8 micro-tile (f32x2). smem = 48 KB exactly.
// ---------------------------------------------------------------------------
__global__ __launch_bounds__(256)
void tokens_kernel(const float* __restrict__ projW, const float* __restrict__ projb,
                   float* __restrict__ out)
{
    __shared__ float As[64 * 64];    // As[r][c]  16 KB
    __shared__ float Bs[64 * 128];   // Bs[c][d]  32 KB

    const int tid = threadIdx.x;
    const int r0 = blockIdx.y * 64;
    const int d0 = blockIdx.x * 128;

    for (int i = tid; i < 1024; i += 256) {               // 64 rows x 16 float4
        int r = i >> 4, c4 = i & 15;
        reinterpret_cast<float4*>(As)[r * 16 + c4] =
            *reinterpret_cast<const float4*>(&g_cloud[(size_t)(r0 + r) * KDIM + c4 * 4]);
    }
    for (int i = tid; i < 2048; i += 256) {               // 64 rows x 32 float4
        int c = i >> 5, d4 = i & 31;
        reinterpret_cast<float4*>(Bs)[c * 32 + d4] =
            *reinterpret_cast<const float4*>(&projW[(size_t)c * DMOD + d0 + d4 * 4]);
    }
    __syncthreads();

    const int tx = tid & 15, ty = tid >> 4;

    unsigned long long acc[4][4];
#pragma unroll
    for (int q = 0; q < 4; q++)
#pragma unroll
        for (int j = 0; j < 4; j++) acc[q][j] = 0ull;

#pragma unroll 8
    for (int c = 0; c < 64; c++) {
        ulonglong2 bA = *reinterpret_cast<const ulonglong2*>(&Bs[c * 128 + tx * 8]);
        ulonglong2 bB = *reinterpret_cast<const ulonglong2*>(&Bs[c * 128 + tx * 8 + 4]);
#pragma unroll
        for (int q = 0; q < 4; q++) {
            unsigned long long av = pack_dup(As[(ty * 4 + q) * 64 + c]);
            fma2(acc[q][0], av, bA.x);
            fma2(acc[q][1], av, bA.y);
            fma2(acc[q][2], av, bB.x);
            fma2(acc[q][3], av, bB.y);
        }
    }

    float pb[8];
#pragma unroll
    for (int j = 0; j < 8; j++) pb[j] = projb[d0 + tx * 8 + j];

#pragma unroll
    for (int q = 0; q < 4; q++) {
        size_t row = (size_t)(r0 + ty * 4 + q);
        float4 o1, o2;
        o1.x = lo32(acc[q][0]) + pb[0];
        o1.y = hi32(acc[q][0]) + pb[1];
        o1.z = lo32(acc[q][1]) + pb[2];
        o1.w = hi32(acc[q][1]) + pb[3];
        o2.x = lo32(acc[q][2]) + pb[4];
        o2.y = hi32(acc[q][2]) + pb[5];
        o2.z = lo32(acc[q][3]) + pb[6];
        o2.w = hi32(acc[q][3]) + pb[7];
        *reinterpret_cast<float4*>(&out[row * DMOD + d0 + tx * 8    ]) = o1;
        *reinterpret_cast<float4*>(&out[row * DMOD + d0 + tx * 8 + 4]) = o2;
    }
}

// ---------------------------------------------------------------------------
extern "C" void kernel_launch(void* const* d_in, const int* in_sizes, int n_in,
                              void* d_out, int out_size)
{
    const float* x     = (const float*)d_in[0];
    const float* W1    = (const float*)d_in[1];
    const float* b1    = (const float*)d_in[2];
    const float* W2    = (const float*)d_in[3];
    const float* b2    = (const float*)d_in[4];
    const float* liftW = (const float*)d_in[5];
    const float* liftb = (const float*)d_in[6];
    const float* mu    = (const float*)d_in[7];
    const float* sigma = (const float*)d_in[8];
    const float* projW = (const float*)d_in[9];
    const float* projb = (const float*)d_in[10];

    float* out    = (float*)d_out;
    float* tokens = out;                                   // [32,256,1024]
    float* ystar  = out + (size_t)Bq * KEFF * DMOD;        // [32,4096]

    mlp_kernel  <<<512, 128>>>(x, W1, b1, W2, b2);
    batch_kernel<<<Bq, 1024>>>(ystar);
    lift_kernel <<<Bq * 8, 256>>>(x, liftW, liftb, mu, sigma);
    tokens_kernel<<<dim3(DMOD / 128, (Bq * KEFF) / 64), 256>>>(projW, projb, tokens);
}

// round 6
// speedup vs baseline: 1.5295x; 1.4548x over previous
#include <cuda_runtime.h>
#include <cuda_bf16.h>
#include <cstdint>

// ---------------------------------------------------------------------------
// EncoderSaliencySelection, GB300 sm_103a
// ---------------------------------------------------------------------------

#define Bq   32
#define Nq   4096
#define IDIM 125
#define ADIM 128
#define KDIM 64
#define DMOD 1024
#define HID  64
#define KEFF 256
#define EPSq 1e-6f

__device__ float g_sal [Bq * Nq];
__device__ float g_csal[Bq * Nq];
__device__ int   g_top [Bq * KEFF];
__device__ float g_cloud[Bq * KEFF * KDIM];

// packed f32x2 helpers (element-wise exact: identical rounding to scalar fma)
__device__ __forceinline__ unsigned long long pack_dup(float v) {
    unsigned long long r;
    asm("mov.b64 %0, {%1, %1};" : "=l"(r) : "f"(v));
    return r;
}
__device__ __forceinline__ unsigned long long pack2(float a, float b) {
    unsigned long long r;
    asm("mov.b64 %0, {%1, %2};" : "=l"(r) : "f"(a), "f"(b));
    return r;
}
__device__ __forceinline__ void fma2(unsigned long long& acc,
                                     unsigned long long a, unsigned long long b) {
    asm("fma.rn.f32x2 %0, %1, %2, %0;" : "+l"(acc) : "l"(a), "l"(b));
}
__device__ __forceinline__ float lo32(unsigned long long v) {
    return __uint_as_float((unsigned)(v & 0xffffffffull));
}
__device__ __forceinline__ float hi32(unsigned long long v) {
    return __uint_as_float((unsigned)(v >> 32));
}

// ---------------------------------------------------------------------------
// K1: MLP scorer as tiled GEMM. Block = 128 points x 64 units, 256 threads.
// Thread = 8 points x 4 units (16 ull acc). K=125 in 5 chunks of 25.
// Layer-1: ascending-k fma chain per (point,unit)  [bit-identical to passing]
// Layer-2: strict serial ascending fma over 64      [bit-identical to passing]
// ---------------------------------------------------------------------------
#define CHUNK 25
__global__ __launch_bounds__(256)
void mlp_kernel(const float* __restrict__ x,  const float* __restrict__ W1,
                const float* __restrict__ b1, const float* __restrict__ W2,
                const float* __restrict__ b2)
{
    __shared__ float pool[128 * 65];        // 33280 B; phase1: Xs+Wc, phase2: h
    __shared__ float b1s[HID], W2s[HID];

    float* Xs = pool;                       // [128][26] = 3328 floats
    float* Wc = pool + 128 * 26;            // [25][64]  = 1600 floats

    const int tid = threadIdx.x;
    if (tid < HID) { b1s[tid] = b1[tid]; W2s[tid] = W2[tid]; }

    const int p0 = blockIdx.x * 128;
    const int tx = tid & 15;                // unit group: cols tx*4
    const int ty = tid >> 4;                // point group: rows ty*8

    unsigned long long acc[8][2];
#pragma unroll
    for (int q = 0; q < 8; q++) { acc[q][0] = 0ull; acc[q][1] = 0ull; }

    for (int cc = 0; cc < 5; cc++) {
        __syncthreads();
        // stage W1 chunk [25][64] (contiguous, float4)
        for (int i = tid; i < (CHUNK * HID) / 4; i += 256)
            reinterpret_cast<float4*>(Wc)[i] =
                reinterpret_cast<const float4*>(W1 + cc * CHUNK * HID)[i];
        // stage X chunk: 128 points x 25 cols, pad-26 rows
        for (int i = tid; i < 128 * CHUNK; i += 256) {
            int p = i / CHUNK, c = i - p * CHUNK;
            Xs[p * 26 + c] = x[(size_t)(p0 + p) * IDIM + cc * CHUNK + c];
        }
        __syncthreads();
#pragma unroll
        for (int c = 0; c < CHUNK; c++) {
            ulonglong2 w = *reinterpret_cast<const ulonglong2*>(&Wc[c * HID + tx * 4]);
#pragma unroll
            for (int q = 0; q < 8; q++) {
                unsigned long long av = pack_dup(Xs[(ty * 8 + q) * 26 + c]);
                fma2(acc[q][0], av, w.x);
                fma2(acc[q][1], av, w.y);
            }
        }
    }

    __syncthreads();                        // all reads of Xs/Wc done
    float* hsm = pool;                      // [128][65]
#pragma unroll
    for (int q = 0; q < 8; q++) {
        int p = ty * 8 + q;
        hsm[p * 65 + tx * 4 + 0] = fmaxf(lo32(acc[q][0]) + b1s[tx * 4 + 0], 0.f);
        hsm[p * 65 + tx * 4 + 1] = fmaxf(hi32(acc[q][0]) + b1s[tx * 4 + 1], 0.f);
        hsm[p * 65 + tx * 4 + 2] = fmaxf(lo32(acc[q][1]) + b1s[tx * 4 + 2], 0.f);
        hsm[p * 65 + tx * 4 + 3] = fmaxf(hi32(acc[q][1]) + b1s[tx * 4 + 3], 0.f);
    }
    __syncthreads();

    if (tid < 128) {
        float score = 0.f;
        const float* hp = &hsm[tid * 65];
#pragma unroll
        for (int j = 0; j < HID; j++) score = __fmaf_rn(hp[j], W2s[j], score);
        score += b2[0];
        g_sal[p0 + tid] = 1.f / (1.f + expf(-score));
    }
}

// ---------------------------------------------------------------------------
// K2: cumsum + softmax + radix-select top-256 + ranking sort.
// Order identical to jax.lax.top_k(y_star): y desc, ties -> lower index.
// ---------------------------------------------------------------------------
__global__ __launch_bounds__(1024)
void batch_kernel(float* __restrict__ ystar_out)
{
    __shared__ float    tsum[1024];
    __shared__ unsigned kv[Nq];            // y_star bits (positive -> monotonic)
    __shared__ unsigned hA[256], hB[256];
    __shared__ unsigned selv[KEFF];
    __shared__ int      seli[KEFF];
    __shared__ int      ranks[KEFF];
    __shared__ unsigned sh_prefix, sh_krem, sh_gt;

    const int b = blockIdx.x, t = threadIdx.x;

    // ---- load saliency (coalesced float4) ----
    float4 sl = *reinterpret_cast<const float4*>(&g_sal[(size_t)b * Nq + 4 * t]);
    float s0 = sl.x, s1 = sl.y, s2 = sl.z, s3 = sl.w;

    // ---- inclusive cumsum ----
    float l0 = s0, l1 = l0 + s1, l2 = l1 + s2, l3 = l2 + s3;
    tsum[t] = l3;
    __syncthreads();
    for (int off = 1; off < 1024; off <<= 1) {
        float v = tsum[t];
        float add = (t >= off) ? tsum[t - off] : 0.f;
        __syncthreads();
        tsum[t] = v + add;
        __syncthreads();
    }
    float pre = (t > 0) ? tsum[t - 1] : 0.f;
    const float invN = 1.f / (float)Nq;
    {
        float4 c4;
        c4.x = (pre + l0) * invN; c4.y = (pre + l1) * invN;
        c4.z = (pre + l2) * invN; c4.w = (pre + l3) * invN;
        *reinterpret_cast<float4*>(&g_csal[(size_t)b * Nq + 4 * t]) = c4;
    }
    __syncthreads();

    // ---- softmax(s / 0.5) ----
    tsum[t] = fmaxf(fmaxf(s0, s1), fmaxf(s2, s3));
    __syncthreads();
    for (int off = 512; off > 0; off >>= 1) {
        if (t < off) tsum[t] = fmaxf(tsum[t], tsum[t + off]);
        __syncthreads();
    }
    const float mz = tsum[0] * 2.0f;
    __syncthreads();
    float e0 = expf(s0 * 2.0f - mz);
    float e1 = expf(s1 * 2.0f - mz);
    float e2 = expf(s2 * 2.0f - mz);
    float e3 = expf(s3 * 2.0f - mz);
    tsum[t] = (e0 + e1) + (e2 + e3);
    __syncthreads();
    for (int off = 512; off > 0; off >>= 1) {
        if (t < off) tsum[t] = tsum[t] + tsum[t + off];
        __syncthreads();
    }
    const float S = tsum[0];
    float y0 = e0 / S, y1 = e1 / S, y2 = e2 / S, y3 = e3 / S;
    {
        float4 y4; y4.x = y0; y4.y = y1; y4.z = y2; y4.w = y3;
        *reinterpret_cast<float4*>(&ystar_out[(size_t)b * Nq + 4 * t]) = y4;
    }
    kv[4 * t + 0] = __float_as_uint(y0);
    kv[4 * t + 1] = __float_as_uint(y1);
    kv[4 * t + 2] = __float_as_uint(y2);
    kv[4 * t + 3] = __float_as_uint(y3);
    if (t == 0) { sh_prefix = 0u; sh_krem = KEFF; }
    __syncthreads();

    // ---- radix select: find T = 256th-largest bit pattern ----
#pragma unroll
    for (int round = 0; round < 4; round++) {
        const int shift = 24 - 8 * round;
        const unsigned pmask = (round == 0) ? 0u : (0xFFFFFFFFu << (32 - 8 * round));
        const unsigned pfx  = sh_prefix;
        const unsigned krem = sh_krem;
        if (t < 256) hA[t] = 0u;
        __syncthreads();
#pragma unroll
        for (int e = 0; e < 4; e++) {
            unsigned v = kv[4 * t + e];
            if ((v & pmask) == pfx) atomicAdd(&hA[(v >> shift) & 255], 1u);
        }
        __syncthreads();
        // inclusive suffix scan over 256 bins (8 ping-pong steps)
        unsigned* src = hA; unsigned* dst = hB;
        for (int off = 1; off < 256; off <<= 1) {
            if (t < 256) dst[t] = src[t] + ((t + off < 256) ? src[t + off] : 0u);
            __syncthreads();
            unsigned* tmp = src; src = dst; dst = tmp;
        }
        // src[bb] = #candidates with byte >= bb
        if (t < 256) {
            unsigned Sb = src[t];
            unsigned Sn = (t == 255) ? 0u : src[t + 1];
            if (Sb >= krem && Sn < krem) {
                sh_prefix = pfx | ((unsigned)t << shift);
                sh_krem   = krem - Sn;
            }
        }
        __syncthreads();
    }
    const unsigned T = sh_prefix;
    const unsigned need_eq = sh_krem;

    // ---- stable compaction: strictly-greater, then ==T by ascending index ----
    unsigned* uts = reinterpret_cast<unsigned*>(tsum);
    {
        unsigned c = 0;
#pragma unroll
        for (int e = 0; e < 4; e++) c += (kv[4 * t + e] > T);
        uts[t] = c;
        __syncthreads();
        for (int off = 1; off < 1024; off <<= 1) {
            unsigned v = uts[t];
            unsigned add = (t >= off) ? uts[t - off] : 0u;
            __syncthreads();
            uts[t] = v + add;
            __syncthreads();
        }
        if (t == 1023) sh_gt = uts[1023];
        unsigned pos = uts[t] - c;
#pragma unroll
        for (int e = 0; e < 4; e++) {
            int i = 4 * t + e;
            unsigned v = kv[i];
            if (v > T) { selv[pos] = v; seli[pos] = i; pos++; }
        }
        __syncthreads();
    }
    {
        const unsigned gt = sh_gt;
        unsigned c = 0;
#pragma unroll
        for (int e = 0; e < 4; e++) c += (kv[4 * t + e] == T);
        uts[t] = c;
        __syncthreads();
        for (int off = 1; off < 1024; off <<= 1) {
            unsigned v = uts[t];
            unsigned add = (t >= off) ? uts[t - off] : 0u;
            __syncthreads();
            uts[t] = v + add;
            __syncthreads();
        }
        unsigned pos = uts[t] - c;
#pragma unroll
        for (int e = 0; e < 4; e++) {
            int i = 4 * t + e;
            if (kv[i] == T) {
                if (pos < need_eq) { selv[gt + pos] = T; seli[gt + pos] = i; }
                pos++;
            }
        }
        __syncthreads();
    }

    // ---- ranking sort of 256 selected (value desc, idx asc) ----
    if (t < 256) ranks[t] = 0;
    __syncthreads();
    {
        const int i = t & 255, part = t >> 8;       // 4 parts x 64 j's
        const unsigned vi = selv[i];
        const int ii = seli[i];
        int cnt = 0;
#pragma unroll 8
        for (int j = part * 64; j < part * 64 + 64; j++) {
            unsigned vj = selv[j];
            int ij = seli[j];
            cnt += (vj > vi) || (vj == vi && ij < ii);
        }
        if (cnt) atomicAdd(&ranks[i], cnt);
    }
    __syncthreads();
    if (t < 256) g_top[b * KEFF + ranks[t]] = seli[t];
}

// ---------------------------------------------------------------------------
// K3: warp-per-point gather + normalize + lift. Lane l -> outputs {2l,2l+1}.
// ---------------------------------------------------------------------------
__global__ __launch_bounds__(256)
void lift_kernel(const float* __restrict__ x,
                 const float* __restrict__ liftW, const float* __restrict__ liftb,
                 const float* __restrict__ mu,    const float* __restrict__ sigma)
{
    __shared__ float Ws[ADIM * KDIM];   // 32 KB
    __shared__ float mus[ADIM], rs[ADIM], lbs[KDIM];
    __shared__ float wsh[8][ADIM];      // 4 KB

    const int tid = threadIdx.x;
    for (int i = tid; i < (ADIM * KDIM) / 4; i += 256)
        reinterpret_cast<float4*>(Ws)[i] = reinterpret_cast<const float4*>(liftW)[i];
    if (tid < ADIM) { mus[tid] = mu[tid]; rs[tid] = 1.f / sigma[tid]; }
    if (tid < KDIM) lbs[tid] = liftb[tid];

    const int w = tid >> 5, l = tid & 31;
    const int b     = blockIdx.x >> 3;
    const int kbase = (blockIdx.x & 7) * 32;
    __syncthreads();

    for (int it = 0; it < 4; it++) {
        const int k   = kbase + it * 8 + w;
        const int idx = g_top[b * KEFF + k];
        const float* xr = x + ((size_t)b * Nq + idx) * IDIM;

        float v[4];
#pragma unroll
        for (int q = 0; q < 4; q++) {
            int a = q * 32 + l;
            float val;
            if (a < IDIM)       val = xr[a];
            else if (a == 125)  val = g_sal [(size_t)b * Nq + idx];
            else if (a == 126)  val = (float)idx * (1.f / (float)(Nq - 1));
            else                val = g_csal[(size_t)b * Nq + idx];
            v[q] = val;
        }
        float ss = (v[0] * v[0] + v[1] * v[1]) + (v[2] * v[2] + v[3] * v[3]);
#pragma unroll
        for (int o = 16; o > 0; o >>= 1) ss += __shfl_xor_sync(0xffffffffu, ss, o);
        const float sc = 1.f / (sqrtf(ss) + EPSq);
#pragma unroll
        for (int q = 0; q < 4; q++) {
            int a = q * 32 + l;
            wsh[w][a] = (v[q] * sc - mus[a]) * rs[a];
        }
        __syncwarp();

        unsigned long long acc = pack2(lbs[2 * l], lbs[2 * l + 1]);
#pragma unroll 8
        for (int a = 0; a < ADIM; a++) {
            unsigned long long wpair =
                *reinterpret_cast<const unsigned long long*>(&Ws[a * KDIM + 2 * l]);
            fma2(acc, pack_dup(wsh[w][a]), wpair);
        }
        float2 o; o.x = lo32(acc); o.y = hi32(acc);
        *reinterpret_cast<float2*>(&g_cloud[((size_t)b * KEFF + k) * KDIM + 2 * l]) = o;
        __syncwarp();
    }
}

// ---------------------------------------------------------------------------
// K4: tokens = cloud[8192,64] @ projW[64,1024] + projb
// 64x64 tile, 128 threads, thread = 4 rows x 8 cols (f32x2). smem ~33 KB.
// ---------------------------------------------------------------------------
__global__ __launch_bounds__(128)
void tokens_kernel(const float* __restrict__ projW, const float* __restrict__ projb,
                   float* __restrict__ out)
{
    __shared__ float As[64 * 68];    // As[r][c], pad 68 (17*16B rows) ~17.4 KB
    __shared__ float Bs[64 * 64];    // Bs[c][d]  16 KB

    const int tid = threadIdx.x;
    const int r0 = blockIdx.y * 64;
    const int d0 = blockIdx.x * 64;

    for (int i = tid; i < 1024; i += 128) {               // 64 rows x 16 float4
        int r = i >> 4, c4 = i & 15;
        *reinterpret_cast<float4*>(&As[r * 68 + c4 * 4]) =
            *reinterpret_cast<const float4*>(&g_cloud[(size_t)(r0 + r) * KDIM + c4 * 4]);
    }
    for (int i = tid; i < 1024; i += 128) {               // 64 rows x 16 float4
        int c = i >> 4, d4 = i & 15;
        *reinterpret_cast<float4*>(&Bs[c * 64 + d4 * 4]) =
            *reinterpret_cast<const float4*>(&projW[(size_t)c * DMOD + d0 + d4 * 4]);
    }
    __syncthreads();

    const int tx = tid & 7;          // 8 col groups x 8 cols
    const int ty = tid >> 3;         // 16 row groups x 4 rows

    unsigned long long acc[4][4];
#pragma unroll
    for (int q = 0; q < 4; q++)
#pragma unroll
        for (int j = 0; j < 4; j++) acc[q][j] = 0ull;

#pragma unroll 4
    for (int c = 0; c < 64; c++) {
        ulonglong2 bA = *reinterpret_cast<const ulonglong2*>(&Bs[c * 64 + tx * 8]);
        ulonglong2 bB = *reinterpret_cast<const ulonglong2*>(&Bs[c * 64 + tx * 8 + 4]);
#pragma unroll
        for (int q = 0; q < 4; q++) {
            unsigned long long av = pack_dup(As[(ty * 4 + q) * 68 + c]);
            fma2(acc[q][0], av, bA.x);
            fma2(acc[q][1], av, bA.y);
            fma2(acc[q][2], av, bB.x);
            fma2(acc[q][3], av, bB.y);
        }
    }

    float pb[8];
#pragma unroll
    for (int j = 0; j < 8; j++) pb[j] = projb[d0 + tx * 8 + j];

#pragma unroll
    for (int q = 0; q < 4; q++) {
        size_t row = (size_t)(r0 + ty * 4 + q);
        float4 o1, o2;
        o1.x = lo32(acc[q][0]) + pb[0];
        o1.y = hi32(acc[q][0]) + pb[1];
        o1.z = lo32(acc[q][1]) + pb[2];
        o1.w = hi32(acc[q][1]) + pb[3];
        o2.x = lo32(acc[q][2]) + pb[4];
        o2.y = hi32(acc[q][2]) + pb[5];
        o2.z = lo32(acc[q][3]) + pb[6];
        o2.w = hi32(acc[q][3]) + pb[7];
        *reinterpret_cast<float4*>(&out[row * DMOD + d0 + tx * 8    ]) = o1;
        *reinterpret_cast<float4*>(&out[row * DMOD + d0 + tx * 8 + 4]) = o2;
    }
}

// ---------------------------------------------------------------------------
extern "C" void kernel_launch(void* const* d_in, const int* in_sizes, int n_in,
                              void* d_out, int out_size)
{
    const float* x     = (const float*)d_in[0];
    const float* W1    = (const float*)d_in[1];
    const float* b1    = (const float*)d_in[2];
    const float* W2    = (const float*)d_in[3];
    const float* b2    = (const float*)d_in[4];
    const float* liftW = (const float*)d_in[5];
    const float* liftb = (const float*)d_in[6];
    const float* mu    = (const float*)d_in[7];
    const float* sigma = (const float*)d_in[8];
    const float* projW = (const float*)d_in[9];
    const float* projb = (const float*)d_in[10];

    float* out    = (float*)d_out;
    float* tokens = out;                                   // [32,256,1024]
    float* ystar  = out + (size_t)Bq * KEFF * DMOD;        // [32,4096]

    mlp_kernel  <<<(Bq * Nq) / 128, 256>>>(x, W1, b1, W2, b2);
    batch_kernel<<<Bq, 1024>>>(ystar);
    lift_kernel <<<Bq * 8, 256>>>(x, liftW, liftb, mu, sigma);
    tokens_kernel<<<dim3(DMOD / 64, (Bq * KEFF) / 64), 128>>>(projW, projb, tokens);
}

// round 8
// speedup vs baseline: 1.6170x; 1.0572x over previous
#include <cuda_runtime.h>
#include <cuda_bf16.h>
#include <cstdint>

// ---------------------------------------------------------------------------
// EncoderSaliencySelection, GB300 sm_103a
// ---------------------------------------------------------------------------

#define Bq   32
#define Nq   4096
#define IDIM 125
#define ADIM 128
#define KDIM 64
#define DMOD 1024
#define HID  64
#define KEFF 256
#define EPSq 1e-6f

__device__ float g_sal [Bq * Nq];
__device__ float g_csal[Bq * Nq];
__device__ int   g_top [Bq * KEFF];
__device__ float g_cloud[Bq * KEFF * KDIM];

// packed f32x2 helpers (element-wise exact: identical rounding to scalar fma)
__device__ __forceinline__ unsigned long long pack_dup(float v) {
    unsigned long long r;
    asm("mov.b64 %0, {%1, %1};" : "=l"(r) : "f"(v));
    return r;
}
__device__ __forceinline__ unsigned long long pack2(float a, float b) {
    unsigned long long r;
    asm("mov.b64 %0, {%1, %2};" : "=l"(r) : "f"(a), "f"(b));
    return r;
}
__device__ __forceinline__ void fma2(unsigned long long& acc,
                                     unsigned long long a, unsigned long long b) {
    asm("fma.rn.f32x2 %0, %1, %2, %0;" : "+l"(acc) : "l"(a), "l"(b));
}
__device__ __forceinline__ float lo32(unsigned long long v) {
    return __uint_as_float((unsigned)(v & 0xffffffffull));
}
__device__ __forceinline__ float hi32(unsigned long long v) {
    return __uint_as_float((unsigned)(v >> 32));
}

// ---------------------------------------------------------------------------
// K1: MLP scorer tiled GEMM. Block = 128 points x 64 units, 256 threads.
// Thread = 8 points x 4 units. K=125 in 5 chunks of 25 (6 float4 + 1 scalar).
// Per-(point,unit) fma chain ascending-k: bit-identical to passing version.
// ---------------------------------------------------------------------------
#define CHUNK 25
__global__ __launch_bounds__(256)
void mlp_kernel(const float* __restrict__ x,  const float* __restrict__ W1,
                const float* __restrict__ b1, const float* __restrict__ W2,
                const float* __restrict__ b2)
{
    __shared__ float pool[128 * 65];        // phase1: Xs[128][28]+Wc[25][64]; phase2: h
    __shared__ float b1s[HID], W2s[HID];

    float* Xs = pool;                       // [128][28] = 3584 floats
    float* Wc = pool + 128 * 28;            // [25][64]  = 1600 floats

    const int tid = threadIdx.x;
    if (tid < HID) { b1s[tid] = b1[tid]; W2s[tid] = W2[tid]; }

    const int p0 = blockIdx.x * 128;
    const int tx = tid & 15;                // unit group: cols tx*4
    const int ty = tid >> 4;                // point group: rows ty*8

    unsigned long long acc[8][2];
#pragma unroll
    for (int q = 0; q < 8; q++) { acc[q][0] = 0ull; acc[q][1] = 0ull; }

    for (int cc = 0; cc < 5; cc++) {
        __syncthreads();
        for (int i = tid; i < (CHUNK * HID) / 4; i += 256)
            reinterpret_cast<float4*>(Wc)[i] =
                reinterpret_cast<const float4*>(W1 + cc * CHUNK * HID)[i];
        for (int i = tid; i < 128 * CHUNK; i += 256) {
            int p = i / CHUNK, c = i - p * CHUNK;
            Xs[p * 28 + c] = x[(size_t)(p0 + p) * IDIM + cc * CHUNK + c];
        }
        __syncthreads();

        // cols 0..23 as 6 x float4, per 4-point half
#pragma unroll
        for (int c4 = 0; c4 < 6; c4++) {
#pragma unroll
            for (int half = 0; half < 2; half++) {
                float4 xa[4];
#pragma unroll
                for (int q = 0; q < 4; q++)
                    xa[q] = *reinterpret_cast<const float4*>(
                        &Xs[(ty * 8 + half * 4 + q) * 28 + c4 * 4]);
#pragma unroll
                for (int j = 0; j < 4; j++) {
                    ulonglong2 w = *reinterpret_cast<const ulonglong2*>(
                        &Wc[(c4 * 4 + j) * HID + tx * 4]);
#pragma unroll
                    for (int q = 0; q < 4; q++) {
                        float xv = (j == 0) ? xa[q].x : (j == 1) ? xa[q].y
                                 : (j == 2) ? xa[q].z : xa[q].w;
                        unsigned long long av = pack_dup(xv);
                        fma2(acc[half * 4 + q][0], av, w.x);
                        fma2(acc[half * 4 + q][1], av, w.y);
                    }
                }
            }
        }
        // col 24 scalar
        {
            ulonglong2 w = *reinterpret_cast<const ulonglong2*>(&Wc[24 * HID + tx * 4]);
#pragma unroll
            for (int q = 0; q < 8; q++) {
                unsigned long long av = pack_dup(Xs[(ty * 8 + q) * 28 + 24]);
                fma2(acc[q][0], av, w.x);
                fma2(acc[q][1], av, w.y);
            }
        }
    }

    __syncthreads();
    float* hsm = pool;                      // [128][65]
#pragma unroll
    for (int q = 0; q < 8; q++) {
        int p = ty * 8 + q;
        hsm[p * 65 + tx * 4 + 0] = fmaxf(lo32(acc[q][0]) + b1s[tx * 4 + 0], 0.f);
        hsm[p * 65 + tx * 4 + 1] = fmaxf(hi32(acc[q][0]) + b1s[tx * 4 + 1], 0.f);
        hsm[p * 65 + tx * 4 + 2] = fmaxf(lo32(acc[q][1]) + b1s[tx * 4 + 2], 0.f);
        hsm[p * 65 + tx * 4 + 3] = fmaxf(hi32(acc[q][1]) + b1s[tx * 4 + 3], 0.f);
    }
    __syncthreads();

    if (tid < 128) {
        float score = 0.f;
        const float* hp = &hsm[tid * 65];
#pragma unroll
        for (int j = 0; j < HID; j++) score = __fmaf_rn(hp[j], W2s[j], score);
        score += b2[0];
        g_sal[p0 + tid] = 1.f / (1.f + expf(-score));
    }
}

// ---------------------------------------------------------------------------
// K2: cumsum (shfl, value-only) + softmax with TREE-REDUCED mz/S
// (bit-identical to the R3..R6 passing versions -> selection-safe)
// + radix-select top-256 + ranking sort.
// ---------------------------------------------------------------------------
__global__ __launch_bounds__(1024)
void batch_kernel(float* __restrict__ ystar_out)
{
    __shared__ unsigned kv[Nq];            // 16 KB y_star bits
    __shared__ float    tsum[1024];        //  4 KB (tree reductions, as in R6)
    __shared__ float    fred[32];
    __shared__ unsigned ured[32];
    __shared__ unsigned hA[256], hB[256];
    __shared__ unsigned selv[KEFF];
    __shared__ int      seli[KEFF];
    __shared__ int      ranks[KEFF];
    __shared__ unsigned sh_prefix, sh_krem, sh_gt;

    const int b = blockIdx.x, t = threadIdx.x;
    const int lane = t & 31, wid = t >> 5;

    float4 sl = *reinterpret_cast<const float4*>(&g_sal[(size_t)b * Nq + 4 * t]);
    float s0 = sl.x, s1 = sl.y, s2 = sl.z, s3 = sl.w;

    // ---- inclusive cumsum via shfl (csal is value-tolerant, not selection-critical)
    float l0 = s0, l1 = l0 + s1, l2 = l1 + s2, l3 = l2 + s3;
    float inc = l3;
#pragma unroll
    for (int off = 1; off < 32; off <<= 1) {
        float v = __shfl_up_sync(0xffffffffu, inc, off);
        if (lane >= off) inc += v;
    }
    if (lane == 31) fred[wid] = inc;
    __syncthreads();
    if (wid == 0) {
        float v = fred[lane], sc = v;
#pragma unroll
        for (int off = 1; off < 32; off <<= 1) {
            float u = __shfl_up_sync(0xffffffffu, sc, off);
            if (lane >= off) sc += u;
        }
        fred[lane] = sc - v;               // exclusive prefix of warp totals
    }
    __syncthreads();
    {
        float pre = fred[wid] + (inc - l3);
        const float invN = 1.f / (float)Nq;
        float4 c4;
        c4.x = (pre + l0) * invN; c4.y = (pre + l1) * invN;
        c4.z = (pre + l2) * invN; c4.w = (pre + l3) * invN;
        *reinterpret_cast<float4*>(&g_csal[(size_t)b * Nq + 4 * t]) = c4;
    }

    // ---- softmax max: EXACT R6 tree reduction (selection-critical) ----
    tsum[t] = fmaxf(fmaxf(s0, s1), fmaxf(s2, s3));
    __syncthreads();
    for (int off = 512; off > 0; off >>= 1) {
        if (t < off) tsum[t] = fmaxf(tsum[t], tsum[t + off]);
        __syncthreads();
    }
    const float mz = tsum[0] * 2.0f;
    __syncthreads();
    float e0 = expf(s0 * 2.0f - mz);
    float e1 = expf(s1 * 2.0f - mz);
    float e2 = expf(s2 * 2.0f - mz);
    float e3 = expf(s3 * 2.0f - mz);
    // ---- softmax sum: EXACT R6 tree reduction (selection-critical) ----
    tsum[t] = (e0 + e1) + (e2 + e3);
    __syncthreads();
    for (int off = 512; off > 0; off >>= 1) {
        if (t < off) tsum[t] = tsum[t] + tsum[t + off];
        __syncthreads();
    }
    const float S = tsum[0];
    if (t == 0) { sh_prefix = 0u; sh_krem = KEFF; }
    if (t < 256) hA[t] = 0u;

    float y0 = e0 / S, y1 = e1 / S, y2 = e2 / S, y3 = e3 / S;
    {
        float4 y4; y4.x = y0; y4.y = y1; y4.z = y2; y4.w = y3;
        *reinterpret_cast<float4*>(&ystar_out[(size_t)b * Nq + 4 * t]) = y4;
    }
    kv[4 * t + 0] = __float_as_uint(y0);
    kv[4 * t + 1] = __float_as_uint(y1);
    kv[4 * t + 2] = __float_as_uint(y2);
    kv[4 * t + 3] = __float_as_uint(y3);
    __syncthreads();

    // ---- radix select (4 x 8-bit, MSB first) ----
#pragma unroll
    for (int round = 0; round < 4; round++) {
        const int shift = 24 - 8 * round;
        const unsigned pmask = (round == 0) ? 0u : (0xFFFFFFFFu << (32 - 8 * round));
        const unsigned pfx  = sh_prefix;
        const unsigned krem = sh_krem;
#pragma unroll
        for (int e = 0; e < 4; e++) {
            unsigned v = kv[4 * t + e];
            if ((v & pmask) == pfx) atomicAdd(&hA[(v >> shift) & 255], 1u);
        }
        __syncthreads();
        if (wid == 0) {                    // suffix scan of 256 bins by warp 0
            unsigned loc[8], tot = 0;
#pragma unroll
            for (int j = 0; j < 8; j++) { loc[j] = hA[lane * 8 + j]; tot += loc[j]; }
            unsigned suf = tot;
#pragma unroll
            for (int off = 1; off < 32; off <<= 1) {
                unsigned v = __shfl_down_sync(0xffffffffu, suf, off);
                if (lane + off < 32) suf += v;
            }
            unsigned run = suf - tot;      // strictly-higher lanes
#pragma unroll
            for (int j = 7; j >= 0; j--) { run += loc[j]; hB[lane * 8 + j] = run; }
        }
        __syncthreads();
        if (t < 256) {
            unsigned Sb = hB[t];
            unsigned Sn = (t == 255) ? 0u : hB[t + 1];
            if (Sb >= krem && Sn < krem) {
                sh_prefix = pfx | ((unsigned)t << shift);
                sh_krem   = krem - Sn;
            }
            hA[t] = 0u;                    // prep next round
        }
        __syncthreads();
    }
    const unsigned T = sh_prefix;
    const unsigned need_eq = sh_krem;

    // ---- compaction: strictly-greater first (stable by index) ----
    {
        unsigned c = 0;
#pragma unroll
        for (int e = 0; e < 4; e++) c += (kv[4 * t + e] > T);
        unsigned incu = c;
#pragma unroll
        for (int off = 1; off < 32; off <<= 1) {
            unsigned v = __shfl_up_sync(0xffffffffu, incu, off);
            if (lane >= off) incu += v;
        }
        if (lane == 31) ured[wid] = incu;
        __syncthreads();
        if (wid == 0) {
            unsigned v = ured[lane], sc = v;
#pragma unroll
            for (int off = 1; off < 32; off <<= 1) {
                unsigned u = __shfl_up_sync(0xffffffffu, sc, off);
                if (lane >= off) sc += u;
            }
            ured[lane] = sc - v;
        }
        __syncthreads();
        unsigned pos = ured[wid] + incu - c;
        if (t == 1023) sh_gt = pos + c;
#pragma unroll
        for (int e = 0; e < 4; e++) {
            int i = 4 * t + e;
            unsigned v = kv[i];
            if (v > T) { selv[pos] = v; seli[pos] = i; pos++; }
        }
        __syncthreads();
    }
    // ---- == T, ascending index, capped ----
    {
        const unsigned gt = sh_gt;
        unsigned c = 0;
#pragma unroll
        for (int e = 0; e < 4; e++) c += (kv[4 * t + e] == T);
        unsigned incu = c;
#pragma unroll
        for (int off = 1; off < 32; off <<= 1) {
            unsigned v = __shfl_up_sync(0xffffffffu, incu, off);
            if (lane >= off) incu += v;
        }
        if (lane == 31) ured[wid] = incu;
        __syncthreads();
        if (wid == 0) {
            unsigned v = ured[lane], sc = v;
#pragma unroll
            for (int off = 1; off < 32; off <<= 1) {
                unsigned u = __shfl_up_sync(0xffffffffu, sc, off);
                if (lane >= off) sc += u;
            }
            ured[lane] = sc - v;
        }
        __syncthreads();
        unsigned pos = ured[wid] + incu - c;
#pragma unroll
        for (int e = 0; e < 4; e++) {
            int i = 4 * t + e;
            if (kv[i] == T) {
                if (pos < need_eq) { selv[gt + pos] = T; seli[gt + pos] = i; }
                pos++;
            }
        }
        __syncthreads();
    }

    // ---- ranking sort of 256 selected (value desc, idx asc) ----
    if (t < 256) ranks[t] = 0;
    __syncthreads();
    {
        const int i = t & 255, part = t >> 8;
        const unsigned vi = selv[i];
        const int ii = seli[i];
        int cnt = 0;
#pragma unroll 8
        for (int j = part * 64; j < part * 64 + 64; j++) {
            unsigned vj = selv[j];
            int ij = seli[j];
            cnt += (vj > vi) || (vj == vi && ij < ii);
        }
        if (cnt) atomicAdd(&ranks[i], cnt);
    }
    __syncthreads();
    if (t < 256) g_top[b * KEFF + ranks[t]] = seli[t];
}

// ---------------------------------------------------------------------------
// K3: warp-per-point gather + normalize + lift. 64 points per block.
// ---------------------------------------------------------------------------
__global__ __launch_bounds__(256)
void lift_kernel(const float* __restrict__ x,
                 const float* __restrict__ liftW, const float* __restrict__ liftb,
                 const float* __restrict__ mu,    const float* __restrict__ sigma)
{
    __shared__ float Ws[ADIM * KDIM];   // 32 KB
    __shared__ float mus[ADIM], rs[ADIM], lbs[KDIM];
    __shared__ float wsh[8][ADIM];

    const int tid = threadIdx.x;
    for (int i = tid; i < (ADIM * KDIM) / 4; i += 256)
        reinterpret_cast<float4*>(Ws)[i] = reinterpret_cast<const float4*>(liftW)[i];
    if (tid < ADIM) { mus[tid] = mu[tid]; rs[tid] = 1.f / sigma[tid]; }
    if (tid < KDIM) lbs[tid] = liftb[tid];

    const int w = tid >> 5, l = tid & 31;
    const int b     = blockIdx.x >> 2;
    const int kbase = (blockIdx.x & 3) * 64;
    __syncthreads();

    for (int it = 0; it < 8; it++) {
        const int k   = kbase + it * 8 + w;
        const int idx = g_top[b * KEFF + k];
        const float* xr = x + ((size_t)b * Nq + idx) * IDIM;

        float v[4];
#pragma unroll
        for (int q = 0; q < 4; q++) {
            int a = q * 32 + l;
            float val;
            if (a < IDIM)       val = xr[a];
            else if (a == 125)  val = g_sal [(size_t)b * Nq + idx];
            else if (a == 126)  val = (float)idx * (1.f / (float)(Nq - 1));
            else                val = g_csal[(size_t)b * Nq + idx];
            v[q] = val;
        }
        float ss = (v[0] * v[0] + v[1] * v[1]) + (v[2] * v[2] + v[3] * v[3]);
#pragma unroll
        for (int o = 16; o > 0; o >>= 1) ss += __shfl_xor_sync(0xffffffffu, ss, o);
        const float sc = 1.f / (sqrtf(ss) + EPSq);
#pragma unroll
        for (int q = 0; q < 4; q++) {
            int a = q * 32 + l;
            wsh[w][a] = (v[q] * sc - mus[a]) * rs[a];
        }
        __syncwarp();

        unsigned long long acc = pack2(lbs[2 * l], lbs[2 * l + 1]);
#pragma unroll 8
        for (int a = 0; a < ADIM; a++) {
            unsigned long long wpair =
                *reinterpret_cast<const unsigned long long*>(&Ws[a * KDIM + 2 * l]);
            fma2(acc, pack_dup(wsh[w][a]), wpair);
        }
        float2 o; o.x = lo32(acc); o.y = hi32(acc);
        *reinterpret_cast<float2*>(&g_cloud[((size_t)b * KEFF + k) * KDIM + 2 * l]) = o;
        __syncwarp();
    }
}

// ---------------------------------------------------------------------------
// K4: tokens = cloud[8192,64] @ projW[64,1024] + projb
// 128x64 tile, 256 threads, thread = 4 rows x 8 cols, c unrolled by 4
// with float4 As preloads (2 rows per half to bound registers).
// ---------------------------------------------------------------------------
__global__ __launch_bounds__(256)
void tokens_kernel(const float* __restrict__ projW, const float* __restrict__ projb,
                   float* __restrict__ out)
{
    __shared__ float As[128 * 68];   // [r][c] pad-68 (272B rows) ~34.8 KB
    __shared__ float Bs[64 * 64];    // [c][d]  16 KB

    const int tid = threadIdx.x;
    const int r0 = blockIdx.y * 128;
    const int d0 = blockIdx.x * 64;

    for (int i = tid; i < 2048; i += 256) {               // 128 rows x 16 float4
        int r = i >> 4, c4 = i & 15;
        *reinterpret_cast<float4*>(&As[r * 68 + c4 * 4]) =
            *reinterpret_cast<const float4*>(&g_cloud[(size_t)(r0 + r) * KDIM + c4 * 4]);
    }
    for (int i = tid; i < 1024; i += 256) {               // 64 rows x 16 float4
        int c = i >> 4, d4 = i & 15;
        *reinterpret_cast<float4*>(&Bs[c * 64 + d4 * 4]) =
            *reinterpret_cast<const float4*>(&projW[(size_t)c * DMOD + d0 + d4 * 4]);
    }
    __syncthreads();

    const int tx = tid & 7;          // 8 col groups x 8 cols
    const int ty = tid >> 3;         // 32 row groups x 4 rows

    unsigned long long acc[4][4];
#pragma unroll
    for (int q = 0; q < 4; q++)
#pragma unroll
        for (int j = 0; j < 4; j++) acc[q][j] = 0ull;

#pragma unroll 4
    for (int c4 = 0; c4 < 16; c4++) {
#pragma unroll
        for (int half = 0; half < 2; half++) {
            float4 a0 = *reinterpret_cast<const float4*>(&As[(ty * 4 + half * 2 + 0) * 68 + c4 * 4]);
            float4 a1 = *reinterpret_cast<const float4*>(&As[(ty * 4 + half * 2 + 1) * 68 + c4 * 4]);
#pragma unroll
            for (int j = 0; j < 4; j++) {
                int c = c4 * 4 + j;
                ulonglong2 bA = *reinterpret_cast<const ulonglong2*>(&Bs[c * 64 + tx * 8]);
                ulonglong2 bB = *reinterpret_cast<const ulonglong2*>(&Bs[c * 64 + tx * 8 + 4]);
                float x0 = (j == 0) ? a0.x : (j == 1) ? a0.y : (j == 2) ? a0.z : a0.w;
                float x1 = (j == 0) ? a1.x : (j == 1) ? a1.y : (j == 2) ? a1.z : a1.w;
                unsigned long long av0 = pack_dup(x0);
                unsigned long long av1 = pack_dup(x1);
                int q0 = half * 2, q1 = half * 2 + 1;
                fma2(acc[q0][0], av0, bA.x);
                fma2(acc[q0][1], av0, bA.y);
                fma2(acc[q0][2], av0, bB.x);
                fma2(acc[q0][3], av0, bB.y);
                fma2(acc[q1][0], av1, bA.x);
                fma2(acc[q1][1], av1, bA.y);
                fma2(acc[q1][2], av1, bB.x);
                fma2(acc[q1][3], av1, bB.y);
            }
        }
    }

    float pb[8];
#pragma unroll
    for (int j = 0; j < 8; j++) pb[j] = projb[d0 + tx * 8 + j];

#pragma unroll
    for (int q = 0; q < 4; q++) {
        size_t row = (size_t)(r0 + ty * 4 + q);
        float4 o1, o2;
        o1.x = lo32(acc[q][0]) + pb[0];
        o1.y = hi32(acc[q][0]) + pb[1];
        o1.z = lo32(acc[q][1]) + pb[2];
        o1.w = hi32(acc[q][1]) + pb[3];
        o2.x = lo32(acc[q][2]) + pb[4];
        o2.y = hi32(acc[q][2]) + pb[5];
        o2.z = lo32(acc[q][3]) + pb[6];
        o2.w = hi32(acc[q][3]) + pb[7];
        *reinterpret_cast<float4*>(&out[row * DMOD + d0 + tx * 8    ]) = o1;
        *reinterpret_cast<float4*>(&out[row * DMOD + d0 + tx * 8 + 4]) = o2;
    }
}

// ---------------------------------------------------------------------------
extern "C" void kernel_launch(void* const* d_in, const int* in_sizes, int n_in,
                              void* d_out, int out_size)
{
    const float* x     = (const float*)d_in[0];
    const float* W1    = (const float*)d_in[1];
    const float* b1    = (const float*)d_in[2];
    const float* W2    = (const float*)d_in[3];
    const float* b2    = (const float*)d_in[4];
    const float* liftW = (const float*)d_in[5];
    const float* liftb = (const float*)d_in[6];
    const float* mu    = (const float*)d_in[7];
    const float* sigma = (const float*)d_in[8];
    const float* projW = (const float*)d_in[9];
    const float* projb = (const float*)d_in[10];

    float* out    = (float*)d_out;
    float* tokens = out;                                   // [32,256,1024]
    float* ystar  = out + (size_t)Bq * KEFF * DMOD;        // [32,4096]

    mlp_kernel  <<<(Bq * Nq) / 128, 256>>>(x, W1, b1, W2, b2);
    batch_kernel<<<Bq, 1024>>>(ystar);
    lift_kernel <<<Bq * 4, 256>>>(x, liftW, liftb, mu, sigma);
    tokens_kernel<<<dim3(DMOD / 64, (Bq * KEFF) / 128), 256>>>(projW, projb, tokens);
}

// round 10
// speedup vs baseline: 1.9348x; 1.1965x over previous
#include <cuda_runtime.h>
#include <cuda_bf16.h>
#include <cstdint>

// ---------------------------------------------------------------------------
// EncoderSaliencySelection, GB300 sm_103a (PTX target compute_103: no tcgen05;
// tokens GEMM uses sm_80-style mma.sync tf32 -> fallback HMMA tensor path)
// ---------------------------------------------------------------------------

#define Bq   32
#define Nq   4096
#define IDIM 125
#define ADIM 128
#define KDIM 64
#define DMOD 1024
#define HID  64
#define KEFF 256
#define EPSq 1e-6f

__device__ float g_sal [Bq * Nq];
__device__ float g_csal[Bq * Nq];
__device__ int   g_top [Bq * KEFF];
__device__ float g_cloud[Bq * KEFF * KDIM];

// packed f32x2 helpers (element-wise exact)
__device__ __forceinline__ unsigned long long pack_dup(float v) {
    unsigned long long r;
    asm("mov.b64 %0, {%1, %1};" : "=l"(r) : "f"(v));
    return r;
}
__device__ __forceinline__ unsigned long long pack2(float a, float b) {
    unsigned long long r;
    asm("mov.b64 %0, {%1, %2};" : "=l"(r) : "f"(a), "f"(b));
    return r;
}
__device__ __forceinline__ void fma2(unsigned long long& acc,
                                     unsigned long long a, unsigned long long b) {
    asm("fma.rn.f32x2 %0, %1, %2, %0;" : "+l"(acc) : "l"(a), "l"(b));
}
__device__ __forceinline__ float lo32(unsigned long long v) {
    return __uint_as_float((unsigned)(v & 0xffffffffull));
}
__device__ __forceinline__ float hi32(unsigned long long v) {
    return __uint_as_float((unsigned)(v >> 32));
}
__device__ __forceinline__ uint32_t tf32r(float f) {
    uint32_t u;
    asm("cvt.rna.tf32.f32 %0, %1;" : "=r"(u) : "f"(f));
    return u;
}

// ---------------------------------------------------------------------------
// K1: MLP scorer tiled GEMM (unchanged from R8 passing version)
// ---------------------------------------------------------------------------
#define CHUNK 25
__global__ __launch_bounds__(256)
void mlp_kernel(const float* __restrict__ x,  const float* __restrict__ W1,
                const float* __restrict__ b1, const float* __restrict__ W2,
                const float* __restrict__ b2)
{
    __shared__ float pool[128 * 65];
    __shared__ float b1s[HID], W2s[HID];

    float* Xs = pool;                       // [128][28]
    float* Wc = pool + 128 * 28;            // [25][64]

    const int tid = threadIdx.x;
    if (tid < HID) { b1s[tid] = b1[tid]; W2s[tid] = W2[tid]; }

    const int p0 = blockIdx.x * 128;
    const int tx = tid & 15;
    const int ty = tid >> 4;

    unsigned long long acc[8][2];
#pragma unroll
    for (int q = 0; q < 8; q++) { acc[q][0] = 0ull; acc[q][1] = 0ull; }

    for (int cc = 0; cc < 5; cc++) {
        __syncthreads();
        for (int i = tid; i < (CHUNK * HID) / 4; i += 256)
            reinterpret_cast<float4*>(Wc)[i] =
                reinterpret_cast<const float4*>(W1 + cc * CHUNK * HID)[i];
        for (int i = tid; i < 128 * CHUNK; i += 256) {
            int p = i / CHUNK, c = i - p * CHUNK;
            Xs[p * 28 + c] = x[(size_t)(p0 + p) * IDIM + cc * CHUNK + c];
        }
        __syncthreads();

#pragma unroll
        for (int c4 = 0; c4 < 6; c4++) {
#pragma unroll
            for (int half = 0; half < 2; half++) {
                float4 xa[4];
#pragma unroll
                for (int q = 0; q < 4; q++)
                    xa[q] = *reinterpret_cast<const float4*>(
                        &Xs[(ty * 8 + half * 4 + q) * 28 + c4 * 4]);
#pragma unroll
                for (int j = 0; j < 4; j++) {
                    ulonglong2 w = *reinterpret_cast<const ulonglong2*>(
                        &Wc[(c4 * 4 + j) * HID + tx * 4]);
#pragma unroll
                    for (int q = 0; q < 4; q++) {
                        float xv = (j == 0) ? xa[q].x : (j == 1) ? xa[q].y
                                 : (j == 2) ? xa[q].z : xa[q].w;
                        unsigned long long av = pack_dup(xv);
                        fma2(acc[half * 4 + q][0], av, w.x);
                        fma2(acc[half * 4 + q][1], av, w.y);
                    }
                }
            }
        }
        {
            ulonglong2 w = *reinterpret_cast<const ulonglong2*>(&Wc[24 * HID + tx * 4]);
#pragma unroll
            for (int q = 0; q < 8; q++) {
                unsigned long long av = pack_dup(Xs[(ty * 8 + q) * 28 + 24]);
                fma2(acc[q][0], av, w.x);
                fma2(acc[q][1], av, w.y);
            }
        }
    }

    __syncthreads();
    float* hsm = pool;                      // [128][65]
#pragma unroll
    for (int q = 0; q < 8; q++) {
        int p = ty * 8 + q;
        hsm[p * 65 + tx * 4 + 0] = fmaxf(lo32(acc[q][0]) + b1s[tx * 4 + 0], 0.f);
        hsm[p * 65 + tx * 4 + 1] = fmaxf(hi32(acc[q][0]) + b1s[tx * 4 + 1], 0.f);
        hsm[p * 65 + tx * 4 + 2] = fmaxf(lo32(acc[q][1]) + b1s[tx * 4 + 2], 0.f);
        hsm[p * 65 + tx * 4 + 3] = fmaxf(hi32(acc[q][1]) + b1s[tx * 4 + 3], 0.f);
    }
    __syncthreads();

    if (tid < 128) {
        float score = 0.f;
        const float* hp = &hsm[tid * 65];
#pragma unroll
        for (int j = 0; j < HID; j++) score = __fmaf_rn(hp[j], W2s[j], score);
        score += b2[0];
        g_sal[p0 + tid] = 1.f / (1.f + expf(-score));
    }
}

// ---------------------------------------------------------------------------
// K2: cumsum (shfl) + softmax with TREE-REDUCED mz/S (selection-critical,
// bit-identical to R8 passing) + radix-select + ranking sort. Unchanged.
// ---------------------------------------------------------------------------
__global__ __launch_bounds__(1024)
void batch_kernel(float* __restrict__ ystar_out)
{
    __shared__ unsigned kv[Nq];
    __shared__ float    tsum[1024];
    __shared__ float    fred[32];
    __shared__ unsigned ured[32];
    __shared__ unsigned hA[256], hB[256];
    __shared__ unsigned selv[KEFF];
    __shared__ int      seli[KEFF];
    __shared__ int      ranks[KEFF];
    __shared__ unsigned sh_prefix, sh_krem, sh_gt;

    const int b = blockIdx.x, t = threadIdx.x;
    const int lane = t & 31, wid = t >> 5;

    float4 sl = *reinterpret_cast<const float4*>(&g_sal[(size_t)b * Nq + 4 * t]);
    float s0 = sl.x, s1 = sl.y, s2 = sl.z, s3 = sl.w;

    float l0 = s0, l1 = l0 + s1, l2 = l1 + s2, l3 = l2 + s3;
    float inc = l3;
#pragma unroll
    for (int off = 1; off < 32; off <<= 1) {
        float v = __shfl_up_sync(0xffffffffu, inc, off);
        if (lane >= off) inc += v;
    }
    if (lane == 31) fred[wid] = inc;
    __syncthreads();
    if (wid == 0) {
        float v = fred[lane], sc = v;
#pragma unroll
        for (int off = 1; off < 32; off <<= 1) {
            float u = __shfl_up_sync(0xffffffffu, sc, off);
            if (lane >= off) sc += u;
        }
        fred[lane] = sc - v;
    }
    __syncthreads();
    {
        float pre = fred[wid] + (inc - l3);
        const float invN = 1.f / (float)Nq;
        float4 c4;
        c4.x = (pre + l0) * invN; c4.y = (pre + l1) * invN;
        c4.z = (pre + l2) * invN; c4.w = (pre + l3) * invN;
        *reinterpret_cast<float4*>(&g_csal[(size_t)b * Nq + 4 * t]) = c4;
    }

    tsum[t] = fmaxf(fmaxf(s0, s1), fmaxf(s2, s3));
    __syncthreads();
    for (int off = 512; off > 0; off >>= 1) {
        if (t < off) tsum[t] = fmaxf(tsum[t], tsum[t + off]);
        __syncthreads();
    }
    const float mz = tsum[0] * 2.0f;
    __syncthreads();
    float e0 = expf(s0 * 2.0f - mz);
    float e1 = expf(s1 * 2.0f - mz);
    float e2 = expf(s2 * 2.0f - mz);
    float e3 = expf(s3 * 2.0f - mz);
    tsum[t] = (e0 + e1) + (e2 + e3);
    __syncthreads();
    for (int off = 512; off > 0; off >>= 1) {
        if (t < off) tsum[t] = tsum[t] + tsum[t + off];
        __syncthreads();
    }
    const float S = tsum[0];
    if (t == 0) { sh_prefix = 0u; sh_krem = KEFF; }
    if (t < 256) hA[t] = 0u;

    float y0 = e0 / S, y1 = e1 / S, y2 = e2 / S, y3 = e3 / S;
    {
        float4 y4; y4.x = y0; y4.y = y1; y4.z = y2; y4.w = y3;
        *reinterpret_cast<float4*>(&ystar_out[(size_t)b * Nq + 4 * t]) = y4;
    }
    kv[4 * t + 0] = __float_as_uint(y0);
    kv[4 * t + 1] = __float_as_uint(y1);
    kv[4 * t + 2] = __float_as_uint(y2);
    kv[4 * t + 3] = __float_as_uint(y3);
    __syncthreads();

#pragma unroll
    for (int round = 0; round < 4; round++) {
        const int shift = 24 - 8 * round;
        const unsigned pmask = (round == 0) ? 0u : (0xFFFFFFFFu << (32 - 8 * round));
        const unsigned pfx  = sh_prefix;
        const unsigned krem = sh_krem;
#pragma unroll
        for (int e = 0; e < 4; e++) {
            unsigned v = kv[4 * t + e];
            if ((v & pmask) == pfx) atomicAdd(&hA[(v >> shift) & 255], 1u);
        }
        __syncthreads();
        if (wid == 0) {
            unsigned loc[8], tot = 0;
#pragma unroll
            for (int j = 0; j < 8; j++) { loc[j] = hA[lane * 8 + j]; tot += loc[j]; }
            unsigned suf = tot;
#pragma unroll
            for (int off = 1; off < 32; off <<= 1) {
                unsigned v = __shfl_down_sync(0xffffffffu, suf, off);
                if (lane + off < 32) suf += v;
            }
            unsigned run = suf - tot;
#pragma unroll
            for (int j = 7; j >= 0; j--) { run += loc[j]; hB[lane * 8 + j] = run; }
        }
        __syncthreads();
        if (t < 256) {
            unsigned Sb = hB[t];
            unsigned Sn = (t == 255) ? 0u : hB[t + 1];
            if (Sb >= krem && Sn < krem) {
                sh_prefix = pfx | ((unsigned)t << shift);
                sh_krem   = krem - Sn;
            }
            hA[t] = 0u;
        }
        __syncthreads();
    }
    const unsigned T = sh_prefix;
    const unsigned need_eq = sh_krem;

    {
        unsigned c = 0;
#pragma unroll
        for (int e = 0; e < 4; e++) c += (kv[4 * t + e] > T);
        unsigned incu = c;
#pragma unroll
        for (int off = 1; off < 32; off <<= 1) {
            unsigned v = __shfl_up_sync(0xffffffffu, incu, off);
            if (lane >= off) incu += v;
        }
        if (lane == 31) ured[wid] = incu;
        __syncthreads();
        if (wid == 0) {
            unsigned v = ured[lane], sc = v;
#pragma unroll
            for (int off = 1; off < 32; off <<= 1) {
                unsigned u = __shfl_up_sync(0xffffffffu, sc, off);
                if (lane >= off) sc += u;
            }
            ured[lane] = sc - v;
        }
        __syncthreads();
        unsigned pos = ured[wid] + incu - c;
        if (t == 1023) sh_gt = pos + c;
#pragma unroll
        for (int e = 0; e < 4; e++) {
            int i = 4 * t + e;
            unsigned v = kv[i];
            if (v > T) { selv[pos] = v; seli[pos] = i; pos++; }
        }
        __syncthreads();
    }
    {
        const unsigned gt = sh_gt;
        unsigned c = 0;
#pragma unroll
        for (int e = 0; e < 4; e++) c += (kv[4 * t + e] == T);
        unsigned incu = c;
#pragma unroll
        for (int off = 1; off < 32; off <<= 1) {
            unsigned v = __shfl_up_sync(0xffffffffu, incu, off);
            if (lane >= off) incu += v;
        }
        if (lane == 31) ured[wid] = incu;
        __syncthreads();
        if (wid == 0) {
            unsigned v = ured[lane], sc = v;
#pragma unroll
            for (int off = 1; off < 32; off <<= 1) {
                unsigned u = __shfl_up_sync(0xffffffffu, sc, off);
                if (lane >= off) sc += u;
            }
            ured[lane] = sc - v;
        }
        __syncthreads();
        unsigned pos = ured[wid] + incu - c;
#pragma unroll
        for (int e = 0; e < 4; e++) {
            int i = 4 * t + e;
            if (kv[i] == T) {
                if (pos < need_eq) { selv[gt + pos] = T; seli[gt + pos] = i; }
                pos++;
            }
        }
        __syncthreads();
    }

    if (t < 256) ranks[t] = 0;
    __syncthreads();
    {
        const int i = t & 255, part = t >> 8;
        const unsigned vi = selv[i];
        const int ii = seli[i];
        int cnt = 0;
#pragma unroll 8
        for (int j = part * 64; j < part * 64 + 64; j++) {
            unsigned vj = selv[j];
            int ij = seli[j];
            cnt += (vj > vi) || (vj == vi && ij < ii);
        }
        if (cnt) atomicAdd(&ranks[i], cnt);
    }
    __syncthreads();
    if (t < 256) g_top[b * KEFF + ranks[t]] = seli[t];
}

// ---------------------------------------------------------------------------
// K3: warp-per-point gather + normalize + lift (unchanged from R8)
// ---------------------------------------------------------------------------
__global__ __launch_bounds__(256)
void lift_kernel(const float* __restrict__ x,
                 const float* __restrict__ liftW, const float* __restrict__ liftb,
                 const float* __restrict__ mu,    const float* __restrict__ sigma)
{
    __shared__ float Ws[ADIM * KDIM];
    __shared__ float mus[ADIM], rs[ADIM], lbs[KDIM];
    __shared__ float wsh[8][ADIM];

    const int tid = threadIdx.x;
    for (int i = tid; i < (ADIM * KDIM) / 4; i += 256)
        reinterpret_cast<float4*>(Ws)[i] = reinterpret_cast<const float4*>(liftW)[i];
    if (tid < ADIM) { mus[tid] = mu[tid]; rs[tid] = 1.f / sigma[tid]; }
    if (tid < KDIM) lbs[tid] = liftb[tid];

    const int w = tid >> 5, l = tid & 31;
    const int b     = blockIdx.x >> 2;
    const int kbase = (blockIdx.x & 3) * 64;
    __syncthreads();

    for (int it = 0; it < 8; it++) {
        const int k   = kbase + it * 8 + w;
        const int idx = g_top[b * KEFF + k];
        const float* xr = x + ((size_t)b * Nq + idx) * IDIM;

        float v[4];
#pragma unroll
        for (int q = 0; q < 4; q++) {
            int a = q * 32 + l;
            float val;
            if (a < IDIM)       val = xr[a];
            else if (a == 125)  val = g_sal [(size_t)b * Nq + idx];
            else if (a == 126)  val = (float)idx * (1.f / (float)(Nq - 1));
            else                val = g_csal[(size_t)b * Nq + idx];
            v[q] = val;
        }
        float ss = (v[0] * v[0] + v[1] * v[1]) + (v[2] * v[2] + v[3] * v[3]);
#pragma unroll
        for (int o = 16; o > 0; o >>= 1) ss += __shfl_xor_sync(0xffffffffu, ss, o);
        const float sc = 1.f / (sqrtf(ss) + EPSq);
#pragma unroll
        for (int q = 0; q < 4; q++) {
            int a = q * 32 + l;
            wsh[w][a] = (v[q] * sc - mus[a]) * rs[a];
        }
        __syncwarp();

        unsigned long long acc = pack2(lbs[2 * l], lbs[2 * l + 1]);
#pragma unroll 8
        for (int a = 0; a < ADIM; a++) {
            unsigned long long wpair =
                *reinterpret_cast<const unsigned long long*>(&Ws[a * KDIM + 2 * l]);
            fma2(acc, pack_dup(wsh[w][a]), wpair);
        }
        float2 o; o.x = lo32(acc); o.y = hi32(acc);
        *reinterpret_cast<float2*>(&g_cloud[((size_t)b * KEFF + k) * KDIM + 2 * l]) = o;
        __syncwarp();
    }
}

// ---------------------------------------------------------------------------
// K4: tokens = cloud[8192,64] @ projW[64,1024] + projb via tf32 mma.sync.
// CTA = 128 rows x 128 cols, 256 threads; warp = 16 rows x 128 cols
// = 16 m16n8 tiles x 8 k-steps of m16n8k8.
// As[128][68] tf32, Bs[64][136] tf32 (pad 136 -> conflict-free B frags).
// ---------------------------------------------------------------------------
#define PADA 68
#define PADB 136
#define TK_SMEM ((128 * PADA + 64 * PADB) * 4)

__global__ __launch_bounds__(256)
void tokens_mma_kernel(const float* __restrict__ projW, const float* __restrict__ projb,
                       float* __restrict__ out)
{
    extern __shared__ uint32_t sm[];
    uint32_t* As = sm;                     // [128][PADA]
    uint32_t* Bs = sm + 128 * PADA;        // [64][PADB]

    const int tid = threadIdx.x;
    const int warp = tid >> 5, lane = tid & 31;
    const int qid = lane >> 2, qtd = lane & 3;
    const int r0 = blockIdx.y * 128;
    const int d0 = blockIdx.x * 128;

    // stage A: cloud rows, fp32 -> tf32
    for (int i = tid; i < 2048; i += 256) {
        int r = i >> 4, c4 = i & 15;
        float4 v = *reinterpret_cast<const float4*>(
            &g_cloud[(size_t)(r0 + r) * KDIM + c4 * 4]);
        uint32_t* dst = &As[r * PADA + c4 * 4];
        dst[0] = tf32r(v.x); dst[1] = tf32r(v.y);
        dst[2] = tf32r(v.z); dst[3] = tf32r(v.w);
    }
    // stage B: projW[k][d0+n] -> Bs[k][n], fp32 -> tf32
    for (int i = tid; i < 2048; i += 256) {
        int k = i >> 5, n4 = i & 31;
        float4 v = *reinterpret_cast<const float4*>(
            &projW[(size_t)k * DMOD + d0 + n4 * 4]);
        uint32_t* dst = &Bs[k * PADB + n4 * 4];
        dst[0] = tf32r(v.x); dst[1] = tf32r(v.y);
        dst[2] = tf32r(v.z); dst[3] = tf32r(v.w);
    }
    __syncthreads();

    float c[16][4];
#pragma unroll
    for (int nt = 0; nt < 16; nt++)
#pragma unroll
        for (int j = 0; j < 4; j++) c[nt][j] = 0.f;

#pragma unroll
    for (int ks = 0; ks < 8; ks++) {
        const int k0 = ks * 8;
        const uint32_t* arow = &As[(warp * 16 + qid) * PADA + k0 + qtd];
        uint32_t a0 = arow[0];
        uint32_t a1 = arow[8 * PADA];
        uint32_t a2 = arow[4];
        uint32_t a3 = arow[8 * PADA + 4];
        const uint32_t* brow = &Bs[(k0 + qtd) * PADB + qid];
#pragma unroll
        for (int nt = 0; nt < 16; nt++) {
            uint32_t b0 = brow[nt * 8];
            uint32_t b1 = brow[4 * PADB + nt * 8];
            asm volatile(
                "mma.sync.aligned.m16n8k8.row.col.f32.tf32.tf32.f32 "
                "{%0,%1,%2,%3}, {%4,%5,%6,%7}, {%8,%9}, {%0,%1,%2,%3};"
                : "+f"(c[nt][0]), "+f"(c[nt][1]), "+f"(c[nt][2]), "+f"(c[nt][3])
                : "r"(a0), "r"(a1), "r"(a2), "r"(a3), "r"(b0), "r"(b1));
        }
    }

    // epilogue: c0,c1 -> (row, col..col+1); c2,c3 -> (row+8, ...)
    const size_t rowA = (size_t)(r0 + warp * 16 + qid);
#pragma unroll
    for (int nt = 0; nt < 16; nt++) {
        const int col = d0 + nt * 8 + qtd * 2;
        const float pb0 = projb[col], pb1 = projb[col + 1];
        float2 o1, o2;
        o1.x = c[nt][0] + pb0; o1.y = c[nt][1] + pb1;
        o2.x = c[nt][2] + pb0; o2.y = c[nt][3] + pb1;
        *reinterpret_cast<float2*>(&out[rowA * DMOD + col]) = o1;
        *reinterpret_cast<float2*>(&out[(rowA + 8) * DMOD + col]) = o2;
    }
}

// ---------------------------------------------------------------------------
extern "C" void kernel_launch(void* const* d_in, const int* in_sizes, int n_in,
                              void* d_out, int out_size)
{
    const float* x     = (const float*)d_in[0];
    const float* W1    = (const float*)d_in[1];
    const float* b1    = (const float*)d_in[2];
    const float* W2    = (const float*)d_in[3];
    const float* b2    = (const float*)d_in[4];
    const float* liftW = (const float*)d_in[5];
    const float* liftb = (const float*)d_in[6];
    const float* mu    = (const float*)d_in[7];
    const float* sigma = (const float*)d_in[8];
    const float* projW = (const float*)d_in[9];
    const float* projb = (const float*)d_in[10];

    float* out    = (float*)d_out;
    float* tokens = out;                                   // [32,256,1024]
    float* ystar  = out + (size_t)Bq * KEFF * DMOD;        // [32,4096]

    cudaFuncSetAttribute(tokens_mma_kernel,
                         cudaFuncAttributeMaxDynamicSharedMemorySize, TK_SMEM);

    mlp_kernel  <<<(Bq * Nq) / 128, 256>>>(x, W1, b1, W2, b2);
    batch_kernel<<<Bq, 1024>>>(ystar);
    lift_kernel <<<Bq * 4, 256>>>(x, liftW, liftb, mu, sigma);
    tokens_mma_kernel<<<dim3(DMOD / 128, (Bq * KEFF) / 128), 256, TK_SMEM>>>(
        projW, projb, tokens);
}